// round 13
// baseline (speedup 1.0000x reference)
#include <cuda_runtime.h>
#include <cuda_bf16.h>
#include <cstdint>

// Problem constants
#define Bq 8
#define Fq 256
#define Tq 32
#define Dq 1024
#define NEGV (-1e30f)

// ---------------------------------------------------------------------------
// Device-global scratch (no allocation allowed)
// ---------------------------------------------------------------------------
__device__ float g_tpp[Bq * Tq * Dq];            // txt@Ws + b     (1 MB)
__device__ float g_fp [Bq * Fq * Dq];            // feat@W         (8 MB)

__device__ __nv_bfloat16 g_fh [Bq * Fq * Dq];    // feat hi
__device__ __nv_bfloat16 g_fl [Bq * Fq * Dq];    // feat lo
__device__ __nv_bfloat16 g_th [Bq * Tq * Dq];    // txt hi
__device__ __nv_bfloat16 g_tl [Bq * Tq * Dq];    // txt lo
__device__ __nv_bfloat16 g_wth[Dq * Dq];         // W^T hi  ([n][k])
__device__ __nv_bfloat16 g_wtl[Dq * Dq];         // W^T lo
__device__ __nv_bfloat16 g_wsh[Dq * Dq];         // Ws^T hi
__device__ __nv_bfloat16 g_wsl[Dq * Dq];         // Ws^T lo

// ---------------------------------------------------------------------------
// Helpers
// ---------------------------------------------------------------------------
__device__ __forceinline__ uint32_t smem_to_u32(const void* p) {
    uint32_t a;
    asm("{ .reg .u64 t; cvta.to.shared.u64 t, %1; cvt.u32.u64 %0, t; }"
        : "=r"(a) : "l"(p));
    return a;
}

__device__ __forceinline__ void mma_bf16(float* c, const uint32_t* a, const uint32_t* b) {
    asm volatile(
        "mma.sync.aligned.m16n8k16.row.col.f32.bf16.bf16.f32 "
        "{%0,%1,%2,%3}, {%4,%5,%6,%7}, {%8,%9}, {%0,%1,%2,%3};"
        : "+f"(c[0]), "+f"(c[1]), "+f"(c[2]), "+f"(c[3])
        : "r"(a[0]), "r"(a[1]), "r"(a[2]), "r"(a[3]), "r"(b[0]), "r"(b[1]));
}

#define LDSM_X4(r0, r1, r2, r3, addr)                                        \
    asm volatile("ldmatrix.sync.aligned.m8n8.x4.shared.b16 {%0,%1,%2,%3}, [%4];" \
                 : "=r"(r0), "=r"(r1), "=r"(r2), "=r"(r3) : "r"(addr))

__device__ __forceinline__ void cp16(uint32_t dst, const void* src) {
    asm volatile("cp.async.cg.shared.global [%0], [%1], 16;" :: "r"(dst), "l"(src));
}
#define CP_COMMIT() asm volatile("cp.async.commit_group;" ::: "memory")
#define CP_WAIT1()  asm volatile("cp.async.wait_group 1;" ::: "memory")
#define CP_WAIT0()  asm volatile("cp.async.wait_group 0;" ::: "memory")

// single-MUFU tanh
__device__ __forceinline__ float tanh_mufu(float x) {
    float y;
    asm("tanh.approx.f32 %0, %1;" : "=f"(y) : "f"(x));
    return y;
}
// single-MUFU reciprocal
__device__ __forceinline__ float rcp_mufu(float x) {
    float y;
    asm("rcp.approx.f32 %0, %1;" : "=f"(y) : "f"(x));
    return y;
}
// 2-MUFU accurate tanh (for the per-block film scalars)
__device__ __forceinline__ float ftanh_fast(float x) {
    float e = __expf(2.0f * x);
    return 1.0f - __fdividef(2.0f, e + 1.0f);
}

// ---------------------------------------------------------------------------
// Merged prep: activation hi/lo split + weight transpose/split in ONE launch.
// ---------------------------------------------------------------------------
#define FEAT4 (Bq * Fq * Dq / 4)
#define TXT4  (Bq * Tq * Dq / 4)
#define SPLIT_BLOCKS ((FEAT4 + TXT4 + 255) / 256)   // 2304
#define TRANS_BLOCKS (32 * 32 * 2)                  // 2048

__global__ void __launch_bounds__(256)
prep_kernel(const float* __restrict__ feat, __nv_bfloat16* __restrict__ fh,
            __nv_bfloat16* __restrict__ fl,
            const float* __restrict__ txt, __nv_bfloat16* __restrict__ th,
            __nv_bfloat16* __restrict__ tl,
            const float* __restrict__ W0, __nv_bfloat16* __restrict__ H0,
            __nv_bfloat16* __restrict__ L0,
            const float* __restrict__ W1, __nv_bfloat16* __restrict__ H1,
            __nv_bfloat16* __restrict__ L1) {
    __shared__ float ts[32][33];
    const int blk = blockIdx.x;
    const int tid = threadIdx.x;

    if (blk < SPLIT_BLOCKS) {
        int i = blk * 256 + tid;
        const float* in;
        __nv_bfloat16 *hi, *lo;
        if (i < FEAT4) {
            in = feat; hi = fh; lo = fl;
        } else if (i < FEAT4 + TXT4) {
            i -= FEAT4;
            in = txt; hi = th; lo = tl;
        } else {
            return;
        }
        float4 v = ((const float4*)in)[i];
        __nv_bfloat16 h0 = __float2bfloat16(v.x);
        __nv_bfloat16 h1 = __float2bfloat16(v.y);
        __nv_bfloat16 h2 = __float2bfloat16(v.z);
        __nv_bfloat16 h3 = __float2bfloat16(v.w);
        __nv_bfloat16 l0 = __float2bfloat16(v.x - __bfloat162float(h0));
        __nv_bfloat16 l1 = __float2bfloat16(v.y - __bfloat162float(h1));
        __nv_bfloat16 l2 = __float2bfloat16(v.z - __bfloat162float(h2));
        __nv_bfloat16 l3 = __float2bfloat16(v.w - __bfloat162float(h3));
        ((__nv_bfloat162*)hi)[2 * i]     = __nv_bfloat162(h0, h1);
        ((__nv_bfloat162*)hi)[2 * i + 1] = __nv_bfloat162(h2, h3);
        ((__nv_bfloat162*)lo)[2 * i]     = __nv_bfloat162(l0, l1);
        ((__nv_bfloat162*)lo)[2 * i + 1] = __nv_bfloat162(l2, l3);
    } else {
        const int idx   = blk - SPLIT_BLOCKS;
        const int which = idx >> 10;            // 0 -> W, 1 -> Ws
        const int tile  = idx & 1023;
        const int n0 = (tile & 31) * 32;
        const int k0 = (tile >> 5) * 32;
        const float* in = which ? W1 : W0;
        __nv_bfloat16* hi = which ? H1 : H0;
        __nv_bfloat16* lo = which ? L1 : L0;
        const int tx = tid & 31, ty = tid >> 5;  // (32, 8)
#pragma unroll
        for (int i = 0; i < 32; i += 8)
            ts[ty + i][tx] = in[(size_t)(k0 + ty + i) * Dq + n0 + tx];
        __syncthreads();
#pragma unroll
        for (int i = 0; i < 32; i += 8) {
            float v = ts[tx][ty + i];           // = W[k0+tx][n0+ty+i]
            __nv_bfloat16 h = __float2bfloat16(v);
            __nv_bfloat16 l = __float2bfloat16(v - __bfloat162float(h));
            size_t o = (size_t)(n0 + ty + i) * Dq + k0 + tx;
            hi[o] = h;
            lo[o] = l;
        }
    }
}

// ---------------------------------------------------------------------------
// bf16x3 emulated-fp32 GEMM on mma.sync (m16n8k16 bf16).
// CTA tile 128(m) x 64(n), BK=32, 2-stage cp.async pipeline, 2 CTAs/SM.
// PDL: griddepsync gates the first read of prep outputs.
// ---------------------------------------------------------------------------
#define BK 32
#define NC (Dq / BK)                 // 32
#define ROWB 80                      // 32 bf16 = 64B + 16B pad (conflict-free)
#define ATILE (128 * ROWB)           // 10240
#define BTILE (64 * ROWB)            // 5120
#define OFF_AH 0
#define OFF_AL ATILE
#define OFF_BH (2 * ATILE)
#define OFF_BL (2 * ATILE + BTILE)
#define STAGEB (2 * ATILE + 2 * BTILE)   // 30720
#define SMEM_GEMM (2 * STAGEB)           // 61440

__device__ __forceinline__ void cp_tileA(uint32_t s, const __nv_bfloat16* __restrict__ g,
                                         int row0, int kc, int tid) {
#pragma unroll
    for (int i = 0; i < 2; i++) {
        int idx = tid + (i << 8);          // 0..511
        int r = idx >> 2, c = idx & 3;
        cp16(s + r * ROWB + c * 16, g + (size_t)(row0 + r) * Dq + kc + c * 8);
    }
}
__device__ __forceinline__ void cp_tileB(uint32_t s, const __nv_bfloat16* __restrict__ g,
                                         int row0, int kc, int tid) {
    int r = tid >> 2, c = tid & 3;         // 64 rows x 4 chunks
    cp16(s + r * ROWB + c * 16, g + (size_t)(row0 + r) * Dq + kc + c * 8);
}

__global__ void __launch_bounds__(256, 2)
mma_gemm_kernel(const __nv_bfloat16* __restrict__ A2h, const __nv_bfloat16* __restrict__ A2l,
                const __nv_bfloat16* __restrict__ B2h, const __nv_bfloat16* __restrict__ B2l,
                float* __restrict__ C2,
                const __nv_bfloat16* __restrict__ A1h, const __nv_bfloat16* __restrict__ A1l,
                const __nv_bfloat16* __restrict__ B1h, const __nv_bfloat16* __restrict__ B1l,
                float* __restrict__ C1, const float* __restrict__ bias1) {
    extern __shared__ char sm[];
    const uint32_t smb = smem_to_u32(sm);
    const int tid  = threadIdx.x;
    const int wid  = tid >> 5;
    const int lane = tid & 31;

    const bool st1 = (blockIdx.y >= 16);
    const int  m0  = st1 ? (int)(blockIdx.y - 16) * 128 : (int)blockIdx.y * 128;
    const int  n0  = blockIdx.x * 64;
    const __nv_bfloat16* Ah = st1 ? A1h : A2h;
    const __nv_bfloat16* Al = st1 ? A1l : A2l;
    const __nv_bfloat16* Bh = st1 ? B1h : B2h;
    const __nv_bfloat16* Bl = st1 ? B1l : B2l;
    float* C = st1 ? C1 : C2;

    const int wm = (wid >> 2) * 64;        // warp m offset
    const int wn = (wid & 3) * 16;         // warp n offset

    float acc[4][2][4];
#pragma unroll
    for (int i = 0; i < 4; i++)
#pragma unroll
        for (int j = 0; j < 2; j++)
#pragma unroll
            for (int k = 0; k < 4; k++) acc[i][j][k] = 0.0f;

    // PDL: wait for prep to fully commit its outputs before first read.
    cudaGridDependencySynchronize();

    // prologue: chunk 0
    cp_tileA(smb + OFF_AH, Ah, m0, 0, tid);
    cp_tileA(smb + OFF_AL, Al, m0, 0, tid);
    cp_tileB(smb + OFF_BH, Bh, n0, 0, tid);
    cp_tileB(smb + OFF_BL, Bl, n0, 0, tid);
    CP_COMMIT();

    const int lg = lane >> 3;              // 0..3
    const int lr = lane & 7;

    for (int c = 0; c < NC; c++) {
        if (c + 1 < NC) {
            uint32_t base = smb + ((c + 1) & 1) * STAGEB;
            const int kc = (c + 1) * BK;
            cp_tileA(base + OFF_AH, Ah, m0, kc, tid);
            cp_tileA(base + OFF_AL, Al, m0, kc, tid);
            cp_tileB(base + OFF_BH, Bh, n0, kc, tid);
            cp_tileB(base + OFF_BL, Bl, n0, kc, tid);
            CP_COMMIT();
            CP_WAIT1();
        } else {
            CP_WAIT0();
        }
        __syncthreads();

        const uint32_t base = smb + (c & 1) * STAGEB;

#pragma unroll
        for (int ks = 0; ks < 2; ks++) {
            const int k0 = ks * 16;
            uint32_t bH[2][2], bL[2][2];
            const uint32_t b_off =
                (uint32_t)((wn + ((lg >> 1) << 3) + lr) * ROWB + (k0 + ((lg & 1) << 3)) * 2);
            LDSM_X4(bH[0][0], bH[0][1], bH[1][0], bH[1][1], base + OFF_BH + b_off);
            LDSM_X4(bL[0][0], bL[0][1], bL[1][0], bL[1][1], base + OFF_BL + b_off);

            const uint32_t a_off =
                (uint32_t)((wm + ((lg & 1) << 3) + lr) * ROWB + (k0 + ((lg >> 1) << 3)) * 2);
#pragma unroll
            for (int mt = 0; mt < 4; mt++) {
                uint32_t aH[4], aL[4];
                LDSM_X4(aH[0], aH[1], aH[2], aH[3],
                        base + OFF_AH + a_off + mt * 16 * ROWB);
                LDSM_X4(aL[0], aL[1], aL[2], aL[3],
                        base + OFF_AL + a_off + mt * 16 * ROWB);
#pragma unroll
                for (int nt = 0; nt < 2; nt++) {
                    mma_bf16(acc[mt][nt], aH, bH[nt]);
                    mma_bf16(acc[mt][nt], aH, bL[nt]);
                    mma_bf16(acc[mt][nt], aL, bH[nt]);
                }
            }
        }
        __syncthreads();
    }

    // Epilogue
    const int row_base = m0 + wm + (lane >> 2);
    const int col_base = n0 + wn + (lane & 3) * 2;
#pragma unroll
    for (int mt = 0; mt < 4; mt++) {
#pragma unroll
        for (int nt = 0; nt < 2; nt++) {
            const int r = row_base + mt * 16;
            const int cc = col_base + nt * 8;
            float2 v01 = make_float2(acc[mt][nt][0], acc[mt][nt][1]);
            float2 v23 = make_float2(acc[mt][nt][2], acc[mt][nt][3]);
            if (st1) {
                float b0 = __ldg(&bias1[cc]);
                float b1 = __ldg(&bias1[cc + 1]);
                v01.x += b0; v01.y += b1;
                v23.x += b0; v23.y += b1;
            }
            *(float2*)&C[(size_t)r * Dq + cc] = v01;
            *(float2*)&C[(size_t)(r + 8) * Dq + cc] = v23;
        }
    }
}

// ---------------------------------------------------------------------------
// Fused attention epilogue, 8 frames per block, single wave (grid 256).
// Uses the EXACT identity tanh(a+b) = (tanh a + tanh b)/(1 + tanh a tanh b):
//   u = tanh(fp) precomputed while staging fp_s (F*D tanh, cheap),
//   v = tanh(tv) once per loaded tpp element (reused across 8 frames),
//   hot loop per element: 1 MUFU.RCP (rt=8) + 4 fma ops — replaces the
//   rt~16 MUFU.TANH wall measured in R5-R11.
// ---------------------------------------------------------------------------
#define FPB 8
__global__ void __launch_bounds__(256, 2)
attn_kernel(const float* __restrict__ feat,
            const float* __restrict__ txt,
            const int*   __restrict__ qmask,
            const float* __restrict__ wv,
            const float* __restrict__ Wcw, const float* __restrict__ bcw,
            const float* __restrict__ Wcb, const float* __restrict__ bcb,
            float* __restrict__ out) {
    const int f0   = blockIdx.x * FPB;     // base bf index
    const int b    = f0 >> 8;              // F = 256
    const int tid  = threadIdx.x;
    const int warp = tid >> 5;
    const int lane = tid & 31;

    __shared__ float fp_s[FPB][Dq];        // 32 KB, holds u = tanh(fp)
    __shared__ float wv_s[Dq];             // 4 KB
    __shared__ float rho_s[FPB][Tq];
    __shared__ float red_s[2][FPB][8];
    __shared__ float scal_s[FPB][2];

    // PDL: wait for the GEMM grid to finish before consuming g_fp / g_tpp.
    cudaGridDependencySynchronize();

    {
        const int i = tid * 4;
#pragma unroll
        for (int j = 0; j < FPB; j++) {
            float4 v = *(const float4*)&g_fp[(size_t)(f0 + j) * Dq + i];
            v.x = tanh_mufu(v.x);
            v.y = tanh_mufu(v.y);
            v.z = tanh_mufu(v.z);
            v.w = tanh_mufu(v.w);
            *(float4*)&fp_s[j][i] = v;
        }
        *(float4*)&wv_s[i] = *(const float4*)&wv[i];
    }
    __syncthreads();

    // rho[j][t] = sum_d (u + v) / (1 + u*v) * w[d],  u=tanh(fp), v=tanh(tpp)
    const float* tpp = g_tpp + (size_t)b * Tq * Dq;
    for (int t = warp; t < Tq; t += 8) {
        const float* tr = tpp + (size_t)t * Dq;
        float a[FPB];
#pragma unroll
        for (int j = 0; j < FPB; j++) a[j] = 0.0f;
#pragma unroll 2
        for (int d = lane * 4; d < Dq; d += 128) {
            float4 tv = *(const float4*)&tr[d];
            tv.x = tanh_mufu(tv.x);
            tv.y = tanh_mufu(tv.y);
            tv.z = tanh_mufu(tv.z);
            tv.w = tanh_mufu(tv.w);
            float4 w4 = *(const float4*)&wv_s[d];
#pragma unroll
            for (int j = 0; j < FPB; j++) {
                float4 u = *(const float4*)&fp_s[j][d];
                float n0 = u.x + tv.x;
                float n1 = u.y + tv.y;
                float n2 = u.z + tv.z;
                float n3 = u.w + tv.w;
                float r0 = rcp_mufu(fmaxf(fmaf(u.x, tv.x, 1.0f), 1e-6f));
                float r1 = rcp_mufu(fmaxf(fmaf(u.y, tv.y, 1.0f), 1e-6f));
                float r2 = rcp_mufu(fmaxf(fmaf(u.z, tv.z, 1.0f), 1e-6f));
                float r3 = rcp_mufu(fmaxf(fmaf(u.w, tv.w, 1.0f), 1e-6f));
                a[j] = fmaf(w4.x, n0 * r0, a[j]);
                a[j] = fmaf(w4.y, n1 * r1, a[j]);
                a[j] = fmaf(w4.z, n2 * r2, a[j]);
                a[j] = fmaf(w4.w, n3 * r3, a[j]);
            }
        }
#pragma unroll
        for (int o = 16; o; o >>= 1)
#pragma unroll
            for (int j = 0; j < FPB; j++)
                a[j] += __shfl_xor_sync(0xffffffffu, a[j], o);
        if (lane == 0) {
            float m = (float)qmask[b * Tq + t];
            float msk = (1.0f - m) * NEGV;
#pragma unroll
            for (int j = 0; j < FPB; j++)
                rho_s[j][t] = a[j] + msk;
        }
    }
    __syncthreads();

    // softmax over T=32 (warps 0..7, one frame each)
    {
        float v = rho_s[warp][lane];
        float mx = v;
#pragma unroll
        for (int o = 16; o; o >>= 1)
            mx = fmaxf(mx, __shfl_xor_sync(0xffffffffu, mx, o));
        float e = __expf(v - mx);
        float s = e;
#pragma unroll
        for (int o = 16; o; o >>= 1)
            s += __shfl_xor_sync(0xffffffffu, s, o);
        rho_s[warp][lane] = e / s;
    }
    __syncthreads();

    // txt_h[j] + two dot products
    const int d0 = tid * 4;
    float4 th[FPB];
#pragma unroll
    for (int j = 0; j < FPB; j++) th[j] = make_float4(0.f, 0.f, 0.f, 0.f);
    const float* tb = txt + (size_t)b * Tq * Dq + d0;
#pragma unroll 2
    for (int t = 0; t < Tq; t++) {
        float4 v = *(const float4*)(tb + (size_t)t * Dq);
#pragma unroll
        for (int j = 0; j < FPB; j++) {
            const float a = rho_s[j][t];
            th[j].x = fmaf(a, v.x, th[j].x);
            th[j].y = fmaf(a, v.y, th[j].y);
            th[j].z = fmaf(a, v.z, th[j].z);
            th[j].w = fmaf(a, v.w, th[j].w);
        }
    }
    float4 cw = *(const float4*)&Wcw[d0];
    float4 cb = *(const float4*)&Wcb[d0];
#pragma unroll
    for (int j = 0; j < FPB; j++) {
        float dw = th[j].x * cw.x + th[j].y * cw.y + th[j].z * cw.z + th[j].w * cw.w;
        float db = th[j].x * cb.x + th[j].y * cb.y + th[j].z * cb.z + th[j].w * cb.w;
#pragma unroll
        for (int o = 16; o; o >>= 1) {
            dw += __shfl_xor_sync(0xffffffffu, dw, o);
            db += __shfl_xor_sync(0xffffffffu, db, o);
        }
        if (lane == 0) {
            red_s[0][j][warp] = dw;
            red_s[1][j][warp] = db;
        }
    }
    __syncthreads();
    if (tid < FPB) {
        float sw = 0.f, sb = 0.f;
#pragma unroll
        for (int i = 0; i < 8; i++) {
            sw += red_s[0][tid][i];
            sb += red_s[1][tid][i];
        }
        scal_s[tid][0] = ftanh_fast(sw + bcw[0]);
        scal_s[tid][1] = ftanh_fast(sb + bcb[0]);
    }
    __syncthreads();

#pragma unroll
    for (int j = 0; j < FPB; j++) {
        const float ws = scal_s[j][0];
        const float bs = scal_s[j][1];
        float4 f = *(const float4*)&feat[(size_t)(f0 + j) * Dq + d0];
        float4 o4;
        o4.x = fmaf(ws, f.x, bs);
        o4.y = fmaf(ws, f.y, bs);
        o4.z = fmaf(ws, f.z, bs);
        o4.w = fmaf(ws, f.w, bs);
        *(float4*)&out[(size_t)(f0 + j) * Dq + d0] = o4;
    }
}

// ---------------------------------------------------------------------------
extern "C" void kernel_launch(void* const* d_in, const int* in_sizes, int n_in,
                              void* d_out, int out_size) {
    const float* features = (const float*)d_in[0];
    const float* txt      = (const float*)d_in[2];
    const int*   qm       = (const int*)  d_in[3];
    const float* Ws       = (const float*)d_in[4];
    const float* W        = (const float*)d_in[5];
    const float* wvec     = (const float*)d_in[6];
    const float* bvec     = (const float*)d_in[7];
    const float* Wcw      = (const float*)d_in[8];
    const float* bcw      = (const float*)d_in[9];
    const float* Wcb      = (const float*)d_in[10];
    const float* bcb      = (const float*)d_in[11];
    float* out = (float*)d_out;

    float *tpp_p, *fp_p;
    __nv_bfloat16 *fh, *fl, *th, *tl, *wth, *wtl, *wsh, *wsl;
    cudaGetSymbolAddress((void**)&tpp_p, g_tpp);
    cudaGetSymbolAddress((void**)&fp_p,  g_fp);
    cudaGetSymbolAddress((void**)&fh,  g_fh);
    cudaGetSymbolAddress((void**)&fl,  g_fl);
    cudaGetSymbolAddress((void**)&th,  g_th);
    cudaGetSymbolAddress((void**)&tl,  g_tl);
    cudaGetSymbolAddress((void**)&wth, g_wth);
    cudaGetSymbolAddress((void**)&wtl, g_wtl);
    cudaGetSymbolAddress((void**)&wsh, g_wsh);
    cudaGetSymbolAddress((void**)&wsl, g_wsl);

    cudaFuncSetAttribute(mma_gemm_kernel,
                         cudaFuncAttributeMaxDynamicSharedMemorySize, SMEM_GEMM);

    // 1) merged prep: activation split + weight transpose/split (one launch)
    prep_kernel<<<SPLIT_BLOCKS + TRANS_BLOCKS, 256>>>(
        features, fh, fl, txt, th, tl,
        W, wth, wtl, Ws, wsh, wsl);

    // PDL attribute: secondary may launch while primary drains; consumer
    // kernels call cudaGridDependencySynchronize() before touching producer
    // outputs.
    cudaLaunchAttribute pdl[1];
    pdl[0].id = cudaLaunchAttributeProgrammaticStreamSerialization;
    pdl[0].val.programmaticStreamSerializationAllowed = 1;

    // 2) merged mma.sync GEMM, 288 CTAs, 2 CTAs/SM — PDL-overlapped with prep
    {
        cudaLaunchConfig_t cfg = {};
        cfg.gridDim = dim3(Dq / 64, 18);
        cfg.blockDim = dim3(256);
        cfg.dynamicSmemBytes = SMEM_GEMM;
        cfg.stream = 0;
        cfg.attrs = pdl;
        cfg.numAttrs = 1;
        cudaLaunchKernelEx(&cfg, mma_gemm_kernel,
                           (const __nv_bfloat16*)fh, (const __nv_bfloat16*)fl,
                           (const __nv_bfloat16*)wth, (const __nv_bfloat16*)wtl,
                           fp_p,
                           (const __nv_bfloat16*)th, (const __nv_bfloat16*)tl,
                           (const __nv_bfloat16*)wsh, (const __nv_bfloat16*)wsl,
                           tpp_p, bvec);
    }

    // 3) fused attention + film epilogue — PDL-overlapped with GEMM tail
    {
        cudaLaunchConfig_t cfg = {};
        cfg.gridDim = dim3(Bq * Fq / FPB);
        cfg.blockDim = dim3(256);
        cfg.dynamicSmemBytes = 0;
        cfg.stream = 0;
        cfg.attrs = pdl;
        cfg.numAttrs = 1;
        cudaLaunchKernelEx(&cfg, attn_kernel,
                           features, txt, qm, wvec,
                           Wcw, bcw, Wcb, bcb, out);
    }
}

// round 14
// speedup vs baseline: 1.1598x; 1.1598x over previous
#include <cuda_runtime.h>
#include <cuda_bf16.h>
#include <cstdint>

// Problem constants
#define Bq 8
#define Fq 256
#define Tq 32
#define Dq 1024
#define NEGV (-1e30f)

// ---------------------------------------------------------------------------
// Device-global scratch (no allocation allowed)
// ---------------------------------------------------------------------------
__device__ float g_tpp[Bq * Tq * Dq];            // txt@Ws + b     (1 MB)
__device__ float g_fp [Bq * Fq * Dq];            // feat@W         (8 MB)

__device__ __nv_bfloat16 g_fh [Bq * Fq * Dq];    // feat hi
__device__ __nv_bfloat16 g_fl [Bq * Fq * Dq];    // feat lo
__device__ __nv_bfloat16 g_th [Bq * Tq * Dq];    // txt hi
__device__ __nv_bfloat16 g_tl [Bq * Tq * Dq];    // txt lo
__device__ __nv_bfloat16 g_wth[Dq * Dq];         // W^T hi  ([n][k])
__device__ __nv_bfloat16 g_wtl[Dq * Dq];         // W^T lo
__device__ __nv_bfloat16 g_wsh[Dq * Dq];         // Ws^T hi
__device__ __nv_bfloat16 g_wsl[Dq * Dq];         // Ws^T lo

// ---------------------------------------------------------------------------
// Helpers
// ---------------------------------------------------------------------------
__device__ __forceinline__ uint32_t smem_to_u32(const void* p) {
    uint32_t a;
    asm("{ .reg .u64 t; cvta.to.shared.u64 t, %1; cvt.u32.u64 %0, t; }"
        : "=r"(a) : "l"(p));
    return a;
}

__device__ __forceinline__ void mma_bf16(float* c, const uint32_t* a, const uint32_t* b) {
    asm volatile(
        "mma.sync.aligned.m16n8k16.row.col.f32.bf16.bf16.f32 "
        "{%0,%1,%2,%3}, {%4,%5,%6,%7}, {%8,%9}, {%0,%1,%2,%3};"
        : "+f"(c[0]), "+f"(c[1]), "+f"(c[2]), "+f"(c[3])
        : "r"(a[0]), "r"(a[1]), "r"(a[2]), "r"(a[3]), "r"(b[0]), "r"(b[1]));
}

#define LDSM_X4(r0, r1, r2, r3, addr)                                        \
    asm volatile("ldmatrix.sync.aligned.m8n8.x4.shared.b16 {%0,%1,%2,%3}, [%4];" \
                 : "=r"(r0), "=r"(r1), "=r"(r2), "=r"(r3) : "r"(addr))

__device__ __forceinline__ void cp16(uint32_t dst, const void* src) {
    asm volatile("cp.async.cg.shared.global [%0], [%1], 16;" :: "r"(dst), "l"(src));
}
#define CP_COMMIT() asm volatile("cp.async.commit_group;" ::: "memory")
#define CP_WAIT2()  asm volatile("cp.async.wait_group 2;" ::: "memory")
#define CP_WAIT1()  asm volatile("cp.async.wait_group 1;" ::: "memory")
#define CP_WAIT0()  asm volatile("cp.async.wait_group 0;" ::: "memory")

// single-MUFU tanh
__device__ __forceinline__ float tanh_mufu(float x) {
    float y;
    asm("tanh.approx.f32 %0, %1;" : "=f"(y) : "f"(x));
    return y;
}
// 2-MUFU accurate tanh (for the per-block film scalars)
__device__ __forceinline__ float ftanh_fast(float x) {
    float e = __expf(2.0f * x);
    return 1.0f - __fdividef(2.0f, e + 1.0f);
}

// ---------------------------------------------------------------------------
// Merged prep: activation hi/lo split + weight transpose/split in ONE launch.
// ---------------------------------------------------------------------------
#define FEAT4 (Bq * Fq * Dq / 4)
#define TXT4  (Bq * Tq * Dq / 4)
#define SPLIT_BLOCKS ((FEAT4 + TXT4 + 255) / 256)   // 2304
#define TRANS_BLOCKS (32 * 32 * 2)                  // 2048

__global__ void __launch_bounds__(256)
prep_kernel(const float* __restrict__ feat, __nv_bfloat16* __restrict__ fh,
            __nv_bfloat16* __restrict__ fl,
            const float* __restrict__ txt, __nv_bfloat16* __restrict__ th,
            __nv_bfloat16* __restrict__ tl,
            const float* __restrict__ W0, __nv_bfloat16* __restrict__ H0,
            __nv_bfloat16* __restrict__ L0,
            const float* __restrict__ W1, __nv_bfloat16* __restrict__ H1,
            __nv_bfloat16* __restrict__ L1) {
    __shared__ float ts[32][33];
    const int blk = blockIdx.x;
    const int tid = threadIdx.x;

    if (blk < SPLIT_BLOCKS) {
        int i = blk * 256 + tid;
        const float* in;
        __nv_bfloat16 *hi, *lo;
        if (i < FEAT4) {
            in = feat; hi = fh; lo = fl;
        } else if (i < FEAT4 + TXT4) {
            i -= FEAT4;
            in = txt; hi = th; lo = tl;
        } else {
            return;
        }
        float4 v = ((const float4*)in)[i];
        __nv_bfloat16 h0 = __float2bfloat16(v.x);
        __nv_bfloat16 h1 = __float2bfloat16(v.y);
        __nv_bfloat16 h2 = __float2bfloat16(v.z);
        __nv_bfloat16 h3 = __float2bfloat16(v.w);
        __nv_bfloat16 l0 = __float2bfloat16(v.x - __bfloat162float(h0));
        __nv_bfloat16 l1 = __float2bfloat16(v.y - __bfloat162float(h1));
        __nv_bfloat16 l2 = __float2bfloat16(v.z - __bfloat162float(h2));
        __nv_bfloat16 l3 = __float2bfloat16(v.w - __bfloat162float(h3));
        ((__nv_bfloat162*)hi)[2 * i]     = __nv_bfloat162(h0, h1);
        ((__nv_bfloat162*)hi)[2 * i + 1] = __nv_bfloat162(h2, h3);
        ((__nv_bfloat162*)lo)[2 * i]     = __nv_bfloat162(l0, l1);
        ((__nv_bfloat162*)lo)[2 * i + 1] = __nv_bfloat162(l2, l3);
    } else {
        const int idx   = blk - SPLIT_BLOCKS;
        const int which = idx >> 10;            // 0 -> W, 1 -> Ws
        const int tile  = idx & 1023;
        const int n0 = (tile & 31) * 32;
        const int k0 = (tile >> 5) * 32;
        const float* in = which ? W1 : W0;
        __nv_bfloat16* hi = which ? H1 : H0;
        __nv_bfloat16* lo = which ? L1 : L0;
        const int tx = tid & 31, ty = tid >> 5;  // (32, 8)
#pragma unroll
        for (int i = 0; i < 32; i += 8)
            ts[ty + i][tx] = in[(size_t)(k0 + ty + i) * Dq + n0 + tx];
        __syncthreads();
#pragma unroll
        for (int i = 0; i < 32; i += 8) {
            float v = ts[tx][ty + i];           // = W[k0+tx][n0+ty+i]
            __nv_bfloat16 h = __float2bfloat16(v);
            __nv_bfloat16 l = __float2bfloat16(v - __bfloat162float(h));
            size_t o = (size_t)(n0 + ty + i) * Dq + k0 + tx;
            hi[o] = h;
            lo[o] = l;
        }
    }
}

// ---------------------------------------------------------------------------
// bf16x3 emulated-fp32 GEMM on mma.sync (m16n8k16 bf16).
// CTA tile 128(m) x 64(n), BK=32, THREE-stage cp.async pipeline, 2 CTAs/SM.
// PDL: griddepsync gates the first read of prep outputs.
// ---------------------------------------------------------------------------
#define BK 32
#define NC (Dq / BK)                 // 32
#define ROWB 80                      // 32 bf16 = 64B + 16B pad (conflict-free)
#define ATILE (128 * ROWB)           // 10240
#define BTILE (64 * ROWB)            // 5120
#define OFF_AH 0
#define OFF_AL ATILE
#define OFF_BH (2 * ATILE)
#define OFF_BL (2 * ATILE + BTILE)
#define STAGEB (2 * ATILE + 2 * BTILE)   // 30720
#define NSTAGE 3
#define SMEM_GEMM (NSTAGE * STAGEB)      // 92160

__device__ __forceinline__ void cp_tileA(uint32_t s, const __nv_bfloat16* __restrict__ g,
                                         int row0, int kc, int tid) {
#pragma unroll
    for (int i = 0; i < 2; i++) {
        int idx = tid + (i << 8);          // 0..511
        int r = idx >> 2, c = idx & 3;
        cp16(s + r * ROWB + c * 16, g + (size_t)(row0 + r) * Dq + kc + c * 8);
    }
}
__device__ __forceinline__ void cp_tileB(uint32_t s, const __nv_bfloat16* __restrict__ g,
                                         int row0, int kc, int tid) {
    int r = tid >> 2, c = tid & 3;         // 64 rows x 4 chunks
    cp16(s + r * ROWB + c * 16, g + (size_t)(row0 + r) * Dq + kc + c * 8);
}

__device__ __forceinline__ void issue_chunk(uint32_t base,
                                            const __nv_bfloat16* Ah, const __nv_bfloat16* Al,
                                            const __nv_bfloat16* Bh, const __nv_bfloat16* Bl,
                                            int m0, int n0, int kc, int tid) {
    cp_tileA(base + OFF_AH, Ah, m0, kc, tid);
    cp_tileA(base + OFF_AL, Al, m0, kc, tid);
    cp_tileB(base + OFF_BH, Bh, n0, kc, tid);
    cp_tileB(base + OFF_BL, Bl, n0, kc, tid);
    CP_COMMIT();
}

__global__ void __launch_bounds__(256, 2)
mma_gemm_kernel(const __nv_bfloat16* __restrict__ A2h, const __nv_bfloat16* __restrict__ A2l,
                const __nv_bfloat16* __restrict__ B2h, const __nv_bfloat16* __restrict__ B2l,
                float* __restrict__ C2,
                const __nv_bfloat16* __restrict__ A1h, const __nv_bfloat16* __restrict__ A1l,
                const __nv_bfloat16* __restrict__ B1h, const __nv_bfloat16* __restrict__ B1l,
                float* __restrict__ C1, const float* __restrict__ bias1) {
    extern __shared__ char sm[];
    const uint32_t smb = smem_to_u32(sm);
    const int tid  = threadIdx.x;
    const int wid  = tid >> 5;
    const int lane = tid & 31;

    const bool st1 = (blockIdx.y >= 16);
    const int  m0  = st1 ? (int)(blockIdx.y - 16) * 128 : (int)blockIdx.y * 128;
    const int  n0  = blockIdx.x * 64;
    const __nv_bfloat16* Ah = st1 ? A1h : A2h;
    const __nv_bfloat16* Al = st1 ? A1l : A2l;
    const __nv_bfloat16* Bh = st1 ? B1h : B2h;
    const __nv_bfloat16* Bl = st1 ? B1l : B2l;
    float* C = st1 ? C1 : C2;

    const int wm = (wid >> 2) * 64;        // warp m offset
    const int wn = (wid & 3) * 16;         // warp n offset

    float acc[4][2][4];
#pragma unroll
    for (int i = 0; i < 4; i++)
#pragma unroll
        for (int j = 0; j < 2; j++)
#pragma unroll
            for (int k = 0; k < 4; k++) acc[i][j][k] = 0.0f;

    // PDL: wait for prep to fully commit its outputs before first read.
    cudaGridDependencySynchronize();

    // prologue: chunks 0 and 1 in flight
    issue_chunk(smb + 0 * STAGEB, Ah, Al, Bh, Bl, m0, n0, 0, tid);
    issue_chunk(smb + 1 * STAGEB, Ah, Al, Bh, Bl, m0, n0, BK, tid);

    const int lg = lane >> 3;              // 0..3
    const int lr = lane & 7;

    for (int c = 0; c < NC; c++) {
        if (c + 2 < NC) {
            issue_chunk(smb + ((c + 2) % NSTAGE) * STAGEB, Ah, Al, Bh, Bl,
                        m0, n0, (c + 2) * BK, tid);
            CP_WAIT2();
        } else if (c + 1 < NC) {
            CP_WAIT1();
        } else {
            CP_WAIT0();
        }
        __syncthreads();

        const uint32_t base = smb + (c % NSTAGE) * STAGEB;

#pragma unroll
        for (int ks = 0; ks < 2; ks++) {
            const int k0 = ks * 16;
            uint32_t bH[2][2], bL[2][2];
            const uint32_t b_off =
                (uint32_t)((wn + ((lg >> 1) << 3) + lr) * ROWB + (k0 + ((lg & 1) << 3)) * 2);
            LDSM_X4(bH[0][0], bH[0][1], bH[1][0], bH[1][1], base + OFF_BH + b_off);
            LDSM_X4(bL[0][0], bL[0][1], bL[1][0], bL[1][1], base + OFF_BL + b_off);

            const uint32_t a_off =
                (uint32_t)((wm + ((lg & 1) << 3) + lr) * ROWB + (k0 + ((lg >> 1) << 3)) * 2);
#pragma unroll
            for (int mt = 0; mt < 4; mt++) {
                uint32_t aH[4], aL[4];
                LDSM_X4(aH[0], aH[1], aH[2], aH[3],
                        base + OFF_AH + a_off + mt * 16 * ROWB);
                LDSM_X4(aL[0], aL[1], aL[2], aL[3],
                        base + OFF_AL + a_off + mt * 16 * ROWB);
#pragma unroll
                for (int nt = 0; nt < 2; nt++) {
                    mma_bf16(acc[mt][nt], aH, bH[nt]);
                    mma_bf16(acc[mt][nt], aH, bL[nt]);
                    mma_bf16(acc[mt][nt], aL, bH[nt]);
                }
            }
        }
        __syncthreads();
    }

    // Epilogue
    const int row_base = m0 + wm + (lane >> 2);
    const int col_base = n0 + wn + (lane & 3) * 2;
#pragma unroll
    for (int mt = 0; mt < 4; mt++) {
#pragma unroll
        for (int nt = 0; nt < 2; nt++) {
            const int r = row_base + mt * 16;
            const int cc = col_base + nt * 8;
            float2 v01 = make_float2(acc[mt][nt][0], acc[mt][nt][1]);
            float2 v23 = make_float2(acc[mt][nt][2], acc[mt][nt][3]);
            if (st1) {
                float b0 = __ldg(&bias1[cc]);
                float b1 = __ldg(&bias1[cc + 1]);
                v01.x += b0; v01.y += b1;
                v23.x += b0; v23.y += b1;
            }
            *(float2*)&C[(size_t)r * Dq + cc] = v01;
            *(float2*)&C[(size_t)(r + 8) * Dq + cc] = v23;
        }
    }
}

// ---------------------------------------------------------------------------
// Fused attention epilogue, 8 frames per block, single wave (grid 256).
// R12-exact body (straight MUFU tanh — identity & f16x2 variants both
// measured slower/worse; this shape is the empirical optimum).
// ---------------------------------------------------------------------------
#define FPB 8
__global__ void __launch_bounds__(256, 2)
attn_kernel(const float* __restrict__ feat,
            const float* __restrict__ txt,
            const int*   __restrict__ qmask,
            const float* __restrict__ wv,
            const float* __restrict__ Wcw, const float* __restrict__ bcw,
            const float* __restrict__ Wcb, const float* __restrict__ bcb,
            float* __restrict__ out) {
    const int f0   = blockIdx.x * FPB;     // base bf index
    const int b    = f0 >> 8;              // F = 256
    const int tid  = threadIdx.x;
    const int warp = tid >> 5;
    const int lane = tid & 31;

    __shared__ float fp_s[FPB][Dq];        // 32 KB
    __shared__ float wv_s[Dq];             // 4 KB
    __shared__ float rho_s[FPB][Tq];
    __shared__ float red_s[2][FPB][8];
    __shared__ float scal_s[FPB][2];

    // PDL: wait for the GEMM grid to finish before consuming g_fp / g_tpp.
    cudaGridDependencySynchronize();

    {
        const int i = tid * 4;
#pragma unroll
        for (int j = 0; j < FPB; j++)
            *(float4*)&fp_s[j][i] = *(const float4*)&g_fp[(size_t)(f0 + j) * Dq + i];
        *(float4*)&wv_s[i] = *(const float4*)&wv[i];
    }
    __syncthreads();

    // rho[j][t] = sum_d tanh(fp[j][d] + tpp[t][d]) * w[d]
    const float* tpp = g_tpp + (size_t)b * Tq * Dq;
    for (int t = warp; t < Tq; t += 8) {
        const float* tr = tpp + (size_t)t * Dq;
        float a[FPB];
#pragma unroll
        for (int j = 0; j < FPB; j++) a[j] = 0.0f;
#pragma unroll 2
        for (int d = lane * 4; d < Dq; d += 128) {
            float4 tv = *(const float4*)&tr[d];
            float4 w4 = *(const float4*)&wv_s[d];
#pragma unroll
            for (int j = 0; j < FPB; j++) {
                float4 f4 = *(const float4*)&fp_s[j][d];
                a[j] += tanh_mufu(f4.x + tv.x) * w4.x + tanh_mufu(f4.y + tv.y) * w4.y
                      + tanh_mufu(f4.z + tv.z) * w4.z + tanh_mufu(f4.w + tv.w) * w4.w;
            }
        }
#pragma unroll
        for (int o = 16; o; o >>= 1)
#pragma unroll
            for (int j = 0; j < FPB; j++)
                a[j] += __shfl_xor_sync(0xffffffffu, a[j], o);
        if (lane == 0) {
            float m = (float)qmask[b * Tq + t];
            float msk = (1.0f - m) * NEGV;
#pragma unroll
            for (int j = 0; j < FPB; j++)
                rho_s[j][t] = a[j] + msk;
        }
    }
    __syncthreads();

    // softmax over T=32 (warps 0..7, one frame each)
    {
        float v = rho_s[warp][lane];
        float mx = v;
#pragma unroll
        for (int o = 16; o; o >>= 1)
            mx = fmaxf(mx, __shfl_xor_sync(0xffffffffu, mx, o));
        float e = __expf(v - mx);
        float s = e;
#pragma unroll
        for (int o = 16; o; o >>= 1)
            s += __shfl_xor_sync(0xffffffffu, s, o);
        rho_s[warp][lane] = e / s;
    }
    __syncthreads();

    // txt_h[j] + two dot products
    const int d0 = tid * 4;
    float4 th[FPB];
#pragma unroll
    for (int j = 0; j < FPB; j++) th[j] = make_float4(0.f, 0.f, 0.f, 0.f);
    const float* tb = txt + (size_t)b * Tq * Dq + d0;
#pragma unroll 2
    for (int t = 0; t < Tq; t++) {
        float4 v = *(const float4*)(tb + (size_t)t * Dq);
#pragma unroll
        for (int j = 0; j < FPB; j++) {
            const float a = rho_s[j][t];
            th[j].x = fmaf(a, v.x, th[j].x);
            th[j].y = fmaf(a, v.y, th[j].y);
            th[j].z = fmaf(a, v.z, th[j].z);
            th[j].w = fmaf(a, v.w, th[j].w);
        }
    }
    float4 cw = *(const float4*)&Wcw[d0];
    float4 cb = *(const float4*)&Wcb[d0];
#pragma unroll
    for (int j = 0; j < FPB; j++) {
        float dw = th[j].x * cw.x + th[j].y * cw.y + th[j].z * cw.z + th[j].w * cw.w;
        float db = th[j].x * cb.x + th[j].y * cb.y + th[j].z * cb.z + th[j].w * cb.w;
#pragma unroll
        for (int o = 16; o; o >>= 1) {
            dw += __shfl_xor_sync(0xffffffffu, dw, o);
            db += __shfl_xor_sync(0xffffffffu, db, o);
        }
        if (lane == 0) {
            red_s[0][j][warp] = dw;
            red_s[1][j][warp] = db;
        }
    }
    __syncthreads();
    if (tid < FPB) {
        float sw = 0.f, sb = 0.f;
#pragma unroll
        for (int i = 0; i < 8; i++) {
            sw += red_s[0][tid][i];
            sb += red_s[1][tid][i];
        }
        scal_s[tid][0] = ftanh_fast(sw + bcw[0]);
        scal_s[tid][1] = ftanh_fast(sb + bcb[0]);
    }
    __syncthreads();

#pragma unroll
    for (int j = 0; j < FPB; j++) {
        const float ws = scal_s[j][0];
        const float bs = scal_s[j][1];
        float4 f = *(const float4*)&feat[(size_t)(f0 + j) * Dq + d0];
        float4 o4;
        o4.x = fmaf(ws, f.x, bs);
        o4.y = fmaf(ws, f.y, bs);
        o4.z = fmaf(ws, f.z, bs);
        o4.w = fmaf(ws, f.w, bs);
        *(float4*)&out[(size_t)(f0 + j) * Dq + d0] = o4;
    }
}

// ---------------------------------------------------------------------------
extern "C" void kernel_launch(void* const* d_in, const int* in_sizes, int n_in,
                              void* d_out, int out_size) {
    const float* features = (const float*)d_in[0];
    const float* txt      = (const float*)d_in[2];
    const int*   qm       = (const int*)  d_in[3];
    const float* Ws       = (const float*)d_in[4];
    const float* W        = (const float*)d_in[5];
    const float* wvec     = (const float*)d_in[6];
    const float* bvec     = (const float*)d_in[7];
    const float* Wcw      = (const float*)d_in[8];
    const float* bcw      = (const float*)d_in[9];
    const float* Wcb      = (const float*)d_in[10];
    const float* bcb      = (const float*)d_in[11];
    float* out = (float*)d_out;

    float *tpp_p, *fp_p;
    __nv_bfloat16 *fh, *fl, *th, *tl, *wth, *wtl, *wsh, *wsl;
    cudaGetSymbolAddress((void**)&tpp_p, g_tpp);
    cudaGetSymbolAddress((void**)&fp_p,  g_fp);
    cudaGetSymbolAddress((void**)&fh,  g_fh);
    cudaGetSymbolAddress((void**)&fl,  g_fl);
    cudaGetSymbolAddress((void**)&th,  g_th);
    cudaGetSymbolAddress((void**)&tl,  g_tl);
    cudaGetSymbolAddress((void**)&wth, g_wth);
    cudaGetSymbolAddress((void**)&wtl, g_wtl);
    cudaGetSymbolAddress((void**)&wsh, g_wsh);
    cudaGetSymbolAddress((void**)&wsl, g_wsl);

    cudaFuncSetAttribute(mma_gemm_kernel,
                         cudaFuncAttributeMaxDynamicSharedMemorySize, SMEM_GEMM);

    // 1) merged prep: activation split + weight transpose/split (one launch)
    prep_kernel<<<SPLIT_BLOCKS + TRANS_BLOCKS, 256>>>(
        features, fh, fl, txt, th, tl,
        W, wth, wtl, Ws, wsh, wsl);

    // PDL attribute
    cudaLaunchAttribute pdl[1];
    pdl[0].id = cudaLaunchAttributeProgrammaticStreamSerialization;
    pdl[0].val.programmaticStreamSerializationAllowed = 1;

    // 2) merged mma.sync GEMM, 288 CTAs, 2 CTAs/SM, 3-stage pipeline
    {
        cudaLaunchConfig_t cfg = {};
        cfg.gridDim = dim3(Dq / 64, 18);
        cfg.blockDim = dim3(256);
        cfg.dynamicSmemBytes = SMEM_GEMM;
        cfg.stream = 0;
        cfg.attrs = pdl;
        cfg.numAttrs = 1;
        cudaLaunchKernelEx(&cfg, mma_gemm_kernel,
                           (const __nv_bfloat16*)fh, (const __nv_bfloat16*)fl,
                           (const __nv_bfloat16*)wth, (const __nv_bfloat16*)wtl,
                           fp_p,
                           (const __nv_bfloat16*)th, (const __nv_bfloat16*)tl,
                           (const __nv_bfloat16*)wsh, (const __nv_bfloat16*)wsl,
                           tpp_p, bvec);
    }

    // 3) fused attention + film epilogue — PDL-overlapped with GEMM tail
    {
        cudaLaunchConfig_t cfg = {};
        cfg.gridDim = dim3(Bq * Fq / FPB);
        cfg.blockDim = dim3(256);
        cfg.dynamicSmemBytes = 0;
        cfg.stream = 0;
        cfg.attrs = pdl;
        cfg.numAttrs = 1;
        cudaLaunchKernelEx(&cfg, attn_kernel,
                           features, txt, qm, wvec,
                           Wcw, bcw, Wcb, bcb, out);
    }
}

// round 15
// speedup vs baseline: 1.1677x; 1.0068x over previous
#include <cuda_runtime.h>
#include <cuda_bf16.h>
#include <cstdint>

// Problem constants
#define Bq 8
#define Fq 256
#define Tq 32
#define Dq 1024
#define NEGV (-1e30f)

// ---------------------------------------------------------------------------
// Device-global scratch (no allocation allowed)
// ---------------------------------------------------------------------------
__device__ float g_tpp[Bq * Tq * Dq];            // txt@Ws + b     (1 MB)
__device__ float g_fp [Bq * Fq * Dq];            // feat@W         (8 MB)

__device__ __nv_bfloat16 g_fh [Bq * Fq * Dq];    // feat hi
__device__ __nv_bfloat16 g_fl [Bq * Fq * Dq];    // feat lo
__device__ __nv_bfloat16 g_th [Bq * Tq * Dq];    // txt hi
__device__ __nv_bfloat16 g_tl [Bq * Tq * Dq];    // txt lo
__device__ __nv_bfloat16 g_wth[Dq * Dq];         // W^T hi  ([n][k])
__device__ __nv_bfloat16 g_wtl[Dq * Dq];         // W^T lo
__device__ __nv_bfloat16 g_wsh[Dq * Dq];         // Ws^T hi
__device__ __nv_bfloat16 g_wsl[Dq * Dq];         // Ws^T lo

// ---------------------------------------------------------------------------
// Helpers
// ---------------------------------------------------------------------------
__device__ __forceinline__ uint32_t smem_to_u32(const void* p) {
    uint32_t a;
    asm("{ .reg .u64 t; cvta.to.shared.u64 t, %1; cvt.u32.u64 %0, t; }"
        : "=r"(a) : "l"(p));
    return a;
}

__device__ __forceinline__ void mma_bf16(float* c, const uint32_t* a, const uint32_t* b) {
    asm volatile(
        "mma.sync.aligned.m16n8k16.row.col.f32.bf16.bf16.f32 "
        "{%0,%1,%2,%3}, {%4,%5,%6,%7}, {%8,%9}, {%0,%1,%2,%3};"
        : "+f"(c[0]), "+f"(c[1]), "+f"(c[2]), "+f"(c[3])
        : "r"(a[0]), "r"(a[1]), "r"(a[2]), "r"(a[3]), "r"(b[0]), "r"(b[1]));
}

#define LDSM_X4(r0, r1, r2, r3, addr)                                        \
    asm volatile("ldmatrix.sync.aligned.m8n8.x4.shared.b16 {%0,%1,%2,%3}, [%4];" \
                 : "=r"(r0), "=r"(r1), "=r"(r2), "=r"(r3) : "r"(addr))

__device__ __forceinline__ void cp16(uint32_t dst, const void* src) {
    asm volatile("cp.async.cg.shared.global [%0], [%1], 16;" :: "r"(dst), "l"(src));
}
#define CP_COMMIT() asm volatile("cp.async.commit_group;" ::: "memory")
#define CP_WAIT1()  asm volatile("cp.async.wait_group 1;" ::: "memory")
#define CP_WAIT0()  asm volatile("cp.async.wait_group 0;" ::: "memory")

// single-MUFU tanh
__device__ __forceinline__ float tanh_mufu(float x) {
    float y;
    asm("tanh.approx.f32 %0, %1;" : "=f"(y) : "f"(x));
    return y;
}
// 2-MUFU accurate tanh (for the per-block film scalars)
__device__ __forceinline__ float ftanh_fast(float x) {
    float e = __expf(2.0f * x);
    return 1.0f - __fdividef(2.0f, e + 1.0f);
}

// ---------------------------------------------------------------------------
// Merged prep: activation hi/lo split + weight transpose/split in ONE launch.
// Triggers PDL completion after its stores so the GEMM grid launches during
// prep's drain.
// ---------------------------------------------------------------------------
#define FEAT4 (Bq * Fq * Dq / 4)
#define TXT4  (Bq * Tq * Dq / 4)
#define SPLIT_BLOCKS ((FEAT4 + TXT4 + 255) / 256)   // 2304
#define TRANS_BLOCKS (32 * 32 * 2)                  // 2048

__global__ void __launch_bounds__(256)
prep_kernel(const float* __restrict__ feat, __nv_bfloat16* __restrict__ fh,
            __nv_bfloat16* __restrict__ fl,
            const float* __restrict__ txt, __nv_bfloat16* __restrict__ th,
            __nv_bfloat16* __restrict__ tl,
            const float* __restrict__ W0, __nv_bfloat16* __restrict__ H0,
            __nv_bfloat16* __restrict__ L0,
            const float* __restrict__ W1, __nv_bfloat16* __restrict__ H1,
            __nv_bfloat16* __restrict__ L1) {
    __shared__ float ts[32][33];
    const int blk = blockIdx.x;
    const int tid = threadIdx.x;

    if (blk < SPLIT_BLOCKS) {
        int i = blk * 256 + tid;
        const float* in = nullptr;
        __nv_bfloat16 *hi = nullptr, *lo = nullptr;
        bool active = true;
        if (i < FEAT4) {
            in = feat; hi = fh; lo = fl;
        } else if (i < FEAT4 + TXT4) {
            i -= FEAT4;
            in = txt; hi = th; lo = tl;
        } else {
            active = false;
        }
        if (active) {
            float4 v = ((const float4*)in)[i];
            __nv_bfloat16 h0 = __float2bfloat16(v.x);
            __nv_bfloat16 h1 = __float2bfloat16(v.y);
            __nv_bfloat16 h2 = __float2bfloat16(v.z);
            __nv_bfloat16 h3 = __float2bfloat16(v.w);
            __nv_bfloat16 l0 = __float2bfloat16(v.x - __bfloat162float(h0));
            __nv_bfloat16 l1 = __float2bfloat16(v.y - __bfloat162float(h1));
            __nv_bfloat16 l2 = __float2bfloat16(v.z - __bfloat162float(h2));
            __nv_bfloat16 l3 = __float2bfloat16(v.w - __bfloat162float(h3));
            ((__nv_bfloat162*)hi)[2 * i]     = __nv_bfloat162(h0, h1);
            ((__nv_bfloat162*)hi)[2 * i + 1] = __nv_bfloat162(h2, h3);
            ((__nv_bfloat162*)lo)[2 * i]     = __nv_bfloat162(l0, l1);
            ((__nv_bfloat162*)lo)[2 * i + 1] = __nv_bfloat162(l2, l3);
        }
    } else {
        const int idx   = blk - SPLIT_BLOCKS;
        const int which = idx >> 10;            // 0 -> W, 1 -> Ws
        const int tile  = idx & 1023;
        const int n0 = (tile & 31) * 32;
        const int k0 = (tile >> 5) * 32;
        const float* in = which ? W1 : W0;
        __nv_bfloat16* hi = which ? H1 : H0;
        __nv_bfloat16* lo = which ? L1 : L0;
        const int tx = tid & 31, ty = tid >> 5;  // (32, 8)
#pragma unroll
        for (int i = 0; i < 32; i += 8)
            ts[ty + i][tx] = in[(size_t)(k0 + ty + i) * Dq + n0 + tx];
        __syncthreads();
#pragma unroll
        for (int i = 0; i < 32; i += 8) {
            float v = ts[tx][ty + i];           // = W[k0+tx][n0+ty+i]
            __nv_bfloat16 h = __float2bfloat16(v);
            __nv_bfloat16 l = __float2bfloat16(v - __bfloat162float(h));
            size_t o = (size_t)(n0 + ty + i) * Dq + k0 + tx;
            hi[o] = h;
            lo[o] = l;
        }
    }
    // PDL: let the dependent GEMM grid launch while this grid drains.
    cudaTriggerProgrammaticLaunchCompletion();
}

// ---------------------------------------------------------------------------
// bf16x3 emulated-fp32 GEMM on mma.sync (m16n8k16 bf16).
// CTA tile 128(m) x 64(n), BK=32, 2-stage cp.async pipeline, 2 CTAs/SM.
// PDL consumer (griddepsync) AND producer (trigger for attn).
// ---------------------------------------------------------------------------
#define BK 32
#define NC (Dq / BK)                 // 32
#define ROWB 80                      // 32 bf16 = 64B + 16B pad (conflict-free)
#define ATILE (128 * ROWB)           // 10240
#define BTILE (64 * ROWB)            // 5120
#define OFF_AH 0
#define OFF_AL ATILE
#define OFF_BH (2 * ATILE)
#define OFF_BL (2 * ATILE + BTILE)
#define STAGEB (2 * ATILE + 2 * BTILE)   // 30720
#define SMEM_GEMM (2 * STAGEB)           // 61440

__device__ __forceinline__ void cp_tileA(uint32_t s, const __nv_bfloat16* __restrict__ g,
                                         int row0, int kc, int tid) {
#pragma unroll
    for (int i = 0; i < 2; i++) {
        int idx = tid + (i << 8);          // 0..511
        int r = idx >> 2, c = idx & 3;
        cp16(s + r * ROWB + c * 16, g + (size_t)(row0 + r) * Dq + kc + c * 8);
    }
}
__device__ __forceinline__ void cp_tileB(uint32_t s, const __nv_bfloat16* __restrict__ g,
                                         int row0, int kc, int tid) {
    int r = tid >> 2, c = tid & 3;         // 64 rows x 4 chunks
    cp16(s + r * ROWB + c * 16, g + (size_t)(row0 + r) * Dq + kc + c * 8);
}

__global__ void __launch_bounds__(256, 2)
mma_gemm_kernel(const __nv_bfloat16* __restrict__ A2h, const __nv_bfloat16* __restrict__ A2l,
                const __nv_bfloat16* __restrict__ B2h, const __nv_bfloat16* __restrict__ B2l,
                float* __restrict__ C2,
                const __nv_bfloat16* __restrict__ A1h, const __nv_bfloat16* __restrict__ A1l,
                const __nv_bfloat16* __restrict__ B1h, const __nv_bfloat16* __restrict__ B1l,
                float* __restrict__ C1, const float* __restrict__ bias1) {
    extern __shared__ char sm[];
    const uint32_t smb = smem_to_u32(sm);
    const int tid  = threadIdx.x;
    const int wid  = tid >> 5;
    const int lane = tid & 31;

    const bool st1 = (blockIdx.y >= 16);
    const int  m0  = st1 ? (int)(blockIdx.y - 16) * 128 : (int)blockIdx.y * 128;
    const int  n0  = blockIdx.x * 64;
    const __nv_bfloat16* Ah = st1 ? A1h : A2h;
    const __nv_bfloat16* Al = st1 ? A1l : A2l;
    const __nv_bfloat16* Bh = st1 ? B1h : B2h;
    const __nv_bfloat16* Bl = st1 ? B1l : B2l;
    float* C = st1 ? C1 : C2;

    const int wm = (wid >> 2) * 64;        // warp m offset
    const int wn = (wid & 3) * 16;         // warp n offset

    float acc[4][2][4];
#pragma unroll
    for (int i = 0; i < 4; i++)
#pragma unroll
        for (int j = 0; j < 2; j++)
#pragma unroll
            for (int k = 0; k < 4; k++) acc[i][j][k] = 0.0f;

    // PDL: wait for prep to fully commit its outputs before first read.
    cudaGridDependencySynchronize();

    // prologue: chunk 0
    cp_tileA(smb + OFF_AH, Ah, m0, 0, tid);
    cp_tileA(smb + OFF_AL, Al, m0, 0, tid);
    cp_tileB(smb + OFF_BH, Bh, n0, 0, tid);
    cp_tileB(smb + OFF_BL, Bl, n0, 0, tid);
    CP_COMMIT();

    const int lg = lane >> 3;              // 0..3
    const int lr = lane & 7;

    for (int c = 0; c < NC; c++) {
        if (c + 1 < NC) {
            uint32_t base = smb + ((c + 1) & 1) * STAGEB;
            const int kc = (c + 1) * BK;
            cp_tileA(base + OFF_AH, Ah, m0, kc, tid);
            cp_tileA(base + OFF_AL, Al, m0, kc, tid);
            cp_tileB(base + OFF_BH, Bh, n0, kc, tid);
            cp_tileB(base + OFF_BL, Bl, n0, kc, tid);
            CP_COMMIT();
            CP_WAIT1();
        } else {
            CP_WAIT0();
        }
        __syncthreads();

        const uint32_t base = smb + (c & 1) * STAGEB;

#pragma unroll
        for (int ks = 0; ks < 2; ks++) {
            const int k0 = ks * 16;
            uint32_t bH[2][2], bL[2][2];
            const uint32_t b_off =
                (uint32_t)((wn + ((lg >> 1) << 3) + lr) * ROWB + (k0 + ((lg & 1) << 3)) * 2);
            LDSM_X4(bH[0][0], bH[0][1], bH[1][0], bH[1][1], base + OFF_BH + b_off);
            LDSM_X4(bL[0][0], bL[0][1], bL[1][0], bL[1][1], base + OFF_BL + b_off);

            const uint32_t a_off =
                (uint32_t)((wm + ((lg & 1) << 3) + lr) * ROWB + (k0 + ((lg >> 1) << 3)) * 2);
#pragma unroll
            for (int mt = 0; mt < 4; mt++) {
                uint32_t aH[4], aL[4];
                LDSM_X4(aH[0], aH[1], aH[2], aH[3],
                        base + OFF_AH + a_off + mt * 16 * ROWB);
                LDSM_X4(aL[0], aL[1], aL[2], aL[3],
                        base + OFF_AL + a_off + mt * 16 * ROWB);
#pragma unroll
                for (int nt = 0; nt < 2; nt++) {
                    mma_bf16(acc[mt][nt], aH, bH[nt]);
                    mma_bf16(acc[mt][nt], aH, bL[nt]);
                    mma_bf16(acc[mt][nt], aL, bH[nt]);
                }
            }
        }
        __syncthreads();
    }

    // Epilogue
    const int row_base = m0 + wm + (lane >> 2);
    const int col_base = n0 + wn + (lane & 3) * 2;
#pragma unroll
    for (int mt = 0; mt < 4; mt++) {
#pragma unroll
        for (int nt = 0; nt < 2; nt++) {
            const int r = row_base + mt * 16;
            const int cc = col_base + nt * 8;
            float2 v01 = make_float2(acc[mt][nt][0], acc[mt][nt][1]);
            float2 v23 = make_float2(acc[mt][nt][2], acc[mt][nt][3]);
            if (st1) {
                float b0 = __ldg(&bias1[cc]);
                float b1 = __ldg(&bias1[cc + 1]);
                v01.x += b0; v01.y += b1;
                v23.x += b0; v23.y += b1;
            }
            *(float2*)&C[(size_t)r * Dq + cc] = v01;
            *(float2*)&C[(size_t)(r + 8) * Dq + cc] = v23;
        }
    }
    // PDL: let attn launch while this grid drains (stores above are ordered
    // before the dependent grid's griddepsync).
    cudaTriggerProgrammaticLaunchCompletion();
}

// ---------------------------------------------------------------------------
// Fused attention epilogue, 8 frames per block, single wave (grid 256).
// R12-exact hot loop; GEMM-independent wv load hoisted above griddepsync.
// ---------------------------------------------------------------------------
#define FPB 8
__global__ void __launch_bounds__(256, 2)
attn_kernel(const float* __restrict__ feat,
            const float* __restrict__ txt,
            const int*   __restrict__ qmask,
            const float* __restrict__ wv,
            const float* __restrict__ Wcw, const float* __restrict__ bcw,
            const float* __restrict__ Wcb, const float* __restrict__ bcb,
            float* __restrict__ out) {
    const int f0   = blockIdx.x * FPB;     // base bf index
    const int b    = f0 >> 8;              // F = 256
    const int tid  = threadIdx.x;
    const int warp = tid >> 5;
    const int lane = tid & 31;

    __shared__ float fp_s[FPB][Dq];        // 32 KB
    __shared__ float wv_s[Dq];             // 4 KB
    __shared__ float rho_s[FPB][Tq];
    __shared__ float red_s[2][FPB][8];
    __shared__ float scal_s[FPB][2];

    const int i0 = tid * 4;
    // GEMM-independent: issue wv load BEFORE the dependency sync so its
    // latency overlaps the wait.
    float4 wv4 = *(const float4*)&wv[i0];

    // PDL: wait for the GEMM grid before consuming g_fp / g_tpp.
    cudaGridDependencySynchronize();

    {
        *(float4*)&wv_s[i0] = wv4;
#pragma unroll
        for (int j = 0; j < FPB; j++)
            *(float4*)&fp_s[j][i0] = *(const float4*)&g_fp[(size_t)(f0 + j) * Dq + i0];
    }
    __syncthreads();

    // rho[j][t] = sum_d tanh(fp[j][d] + tpp[t][d]) * w[d]
    const float* tpp = g_tpp + (size_t)b * Tq * Dq;
    for (int t = warp; t < Tq; t += 8) {
        const float* tr = tpp + (size_t)t * Dq;
        float a[FPB];
#pragma unroll
        for (int j = 0; j < FPB; j++) a[j] = 0.0f;
#pragma unroll 2
        for (int d = lane * 4; d < Dq; d += 128) {
            float4 tv = *(const float4*)&tr[d];
            float4 w4 = *(const float4*)&wv_s[d];
#pragma unroll
            for (int j = 0; j < FPB; j++) {
                float4 f4 = *(const float4*)&fp_s[j][d];
                a[j] += tanh_mufu(f4.x + tv.x) * w4.x + tanh_mufu(f4.y + tv.y) * w4.y
                      + tanh_mufu(f4.z + tv.z) * w4.z + tanh_mufu(f4.w + tv.w) * w4.w;
            }
        }
#pragma unroll
        for (int o = 16; o; o >>= 1)
#pragma unroll
            for (int j = 0; j < FPB; j++)
                a[j] += __shfl_xor_sync(0xffffffffu, a[j], o);
        if (lane == 0) {
            float m = (float)qmask[b * Tq + t];
            float msk = (1.0f - m) * NEGV;
#pragma unroll
            for (int j = 0; j < FPB; j++)
                rho_s[j][t] = a[j] + msk;
        }
    }
    __syncthreads();

    // softmax over T=32 (warps 0..7, one frame each)
    {
        float v = rho_s[warp][lane];
        float mx = v;
#pragma unroll
        for (int o = 16; o; o >>= 1)
            mx = fmaxf(mx, __shfl_xor_sync(0xffffffffu, mx, o));
        float e = __expf(v - mx);
        float s = e;
#pragma unroll
        for (int o = 16; o; o >>= 1)
            s += __shfl_xor_sync(0xffffffffu, s, o);
        rho_s[warp][lane] = e / s;
    }
    __syncthreads();

    // txt_h[j] + two dot products
    const int d0 = tid * 4;
    float4 th[FPB];
#pragma unroll
    for (int j = 0; j < FPB; j++) th[j] = make_float4(0.f, 0.f, 0.f, 0.f);
    const float* tb = txt + (size_t)b * Tq * Dq + d0;
#pragma unroll 2
    for (int t = 0; t < Tq; t++) {
        float4 v = *(const float4*)(tb + (size_t)t * Dq);
#pragma unroll
        for (int j = 0; j < FPB; j++) {
            const float a = rho_s[j][t];
            th[j].x = fmaf(a, v.x, th[j].x);
            th[j].y = fmaf(a, v.y, th[j].y);
            th[j].z = fmaf(a, v.z, th[j].z);
            th[j].w = fmaf(a, v.w, th[j].w);
        }
    }
    float4 cw = *(const float4*)&Wcw[d0];
    float4 cb = *(const float4*)&Wcb[d0];
#pragma unroll
    for (int j = 0; j < FPB; j++) {
        float dw = th[j].x * cw.x + th[j].y * cw.y + th[j].z * cw.z + th[j].w * cw.w;
        float db = th[j].x * cb.x + th[j].y * cb.y + th[j].z * cb.z + th[j].w * cb.w;
#pragma unroll
        for (int o = 16; o; o >>= 1) {
            dw += __shfl_xor_sync(0xffffffffu, dw, o);
            db += __shfl_xor_sync(0xffffffffu, db, o);
        }
        if (lane == 0) {
            red_s[0][j][warp] = dw;
            red_s[1][j][warp] = db;
        }
    }
    __syncthreads();
    if (tid < FPB) {
        float sw = 0.f, sb = 0.f;
#pragma unroll
        for (int i = 0; i < 8; i++) {
            sw += red_s[0][tid][i];
            sb += red_s[1][tid][i];
        }
        scal_s[tid][0] = ftanh_fast(sw + bcw[0]);
        scal_s[tid][1] = ftanh_fast(sb + bcb[0]);
    }
    __syncthreads();

#pragma unroll
    for (int j = 0; j < FPB; j++) {
        const float ws = scal_s[j][0];
        const float bs = scal_s[j][1];
        float4 f = *(const float4*)&feat[(size_t)(f0 + j) * Dq + d0];
        float4 o4;
        o4.x = fmaf(ws, f.x, bs);
        o4.y = fmaf(ws, f.y, bs);
        o4.z = fmaf(ws, f.z, bs);
        o4.w = fmaf(ws, f.w, bs);
        *(float4*)&out[(size_t)(f0 + j) * Dq + d0] = o4;
    }
}

// ---------------------------------------------------------------------------
extern "C" void kernel_launch(void* const* d_in, const int* in_sizes, int n_in,
                              void* d_out, int out_size) {
    const float* features = (const float*)d_in[0];
    const float* txt      = (const float*)d_in[2];
    const int*   qm       = (const int*)  d_in[3];
    const float* Ws       = (const float*)d_in[4];
    const float* W        = (const float*)d_in[5];
    const float* wvec     = (const float*)d_in[6];
    const float* bvec     = (const float*)d_in[7];
    const float* Wcw      = (const float*)d_in[8];
    const float* bcw      = (const float*)d_in[9];
    const float* Wcb      = (const float*)d_in[10];
    const float* bcb      = (const float*)d_in[11];
    float* out = (float*)d_out;

    float *tpp_p, *fp_p;
    __nv_bfloat16 *fh, *fl, *th, *tl, *wth, *wtl, *wsh, *wsl;
    cudaGetSymbolAddress((void**)&tpp_p, g_tpp);
    cudaGetSymbolAddress((void**)&fp_p,  g_fp);
    cudaGetSymbolAddress((void**)&fh,  g_fh);
    cudaGetSymbolAddress((void**)&fl,  g_fl);
    cudaGetSymbolAddress((void**)&th,  g_th);
    cudaGetSymbolAddress((void**)&tl,  g_tl);
    cudaGetSymbolAddress((void**)&wth, g_wth);
    cudaGetSymbolAddress((void**)&wtl, g_wtl);
    cudaGetSymbolAddress((void**)&wsh, g_wsh);
    cudaGetSymbolAddress((void**)&wsl, g_wsl);

    cudaFuncSetAttribute(mma_gemm_kernel,
                         cudaFuncAttributeMaxDynamicSharedMemorySize, SMEM_GEMM);

    // 1) merged prep: activation split + weight transpose/split (one launch)
    prep_kernel<<<SPLIT_BLOCKS + TRANS_BLOCKS, 256>>>(
        features, fh, fl, txt, th, tl,
        W, wth, wtl, Ws, wsh, wsl);

    // PDL attribute
    cudaLaunchAttribute pdl[1];
    pdl[0].id = cudaLaunchAttributeProgrammaticStreamSerialization;
    pdl[0].val.programmaticStreamSerializationAllowed = 1;

    // 2) merged mma.sync GEMM, 288 CTAs, 2 CTAs/SM — PDL-overlapped with prep
    {
        cudaLaunchConfig_t cfg = {};
        cfg.gridDim = dim3(Dq / 64, 18);
        cfg.blockDim = dim3(256);
        cfg.dynamicSmemBytes = SMEM_GEMM;
        cfg.stream = 0;
        cfg.attrs = pdl;
        cfg.numAttrs = 1;
        cudaLaunchKernelEx(&cfg, mma_gemm_kernel,
                           (const __nv_bfloat16*)fh, (const __nv_bfloat16*)fl,
                           (const __nv_bfloat16*)wth, (const __nv_bfloat16*)wtl,
                           fp_p,
                           (const __nv_bfloat16*)th, (const __nv_bfloat16*)tl,
                           (const __nv_bfloat16*)wsh, (const __nv_bfloat16*)wsl,
                           tpp_p, bvec);
    }

    // 3) fused attention + film epilogue — PDL-overlapped with GEMM tail
    {
        cudaLaunchConfig_t cfg = {};
        cfg.gridDim = dim3(Bq * Fq / FPB);
        cfg.blockDim = dim3(256);
        cfg.dynamicSmemBytes = 0;
        cfg.stream = 0;
        cfg.attrs = pdl;
        cfg.numAttrs = 1;
        cudaLaunchKernelEx(&cfg, attn_kernel,
                           features, txt, qm, wvec,
                           Wcw, bcw, Wcb, bcb, out);
    }
}

// round 16
// speedup vs baseline: 1.2424x; 1.0640x over previous
#include <cuda_runtime.h>
#include <cuda_bf16.h>
#include <cstdint>

// Problem constants
#define Bq 8
#define Fq 256
#define Tq 32
#define Dq 1024
#define NEGV (-1e30f)

// ---------------------------------------------------------------------------
// Device-global scratch (no allocation allowed)
// ---------------------------------------------------------------------------
__device__ float g_tpp[Bq * Tq * Dq];            // txt@Ws + b     (1 MB)
__device__ float g_fp [Bq * Fq * Dq];            // feat@W         (8 MB)

__device__ __nv_bfloat16 g_fh [Bq * Fq * Dq];    // feat hi
__device__ __nv_bfloat16 g_fl [Bq * Fq * Dq];    // feat lo
__device__ __nv_bfloat16 g_th [Bq * Tq * Dq];    // txt hi
__device__ __nv_bfloat16 g_tl [Bq * Tq * Dq];    // txt lo
__device__ __nv_bfloat16 g_wth[Dq * Dq];         // W^T hi  ([n][k])
__device__ __nv_bfloat16 g_wtl[Dq * Dq];         // W^T lo
__device__ __nv_bfloat16 g_wsh[Dq * Dq];         // Ws^T hi
__device__ __nv_bfloat16 g_wsl[Dq * Dq];         // Ws^T lo

// ---------------------------------------------------------------------------
// Helpers
// ---------------------------------------------------------------------------
__device__ __forceinline__ uint32_t smem_to_u32(const void* p) {
    uint32_t a;
    asm("{ .reg .u64 t; cvta.to.shared.u64 t, %1; cvt.u32.u64 %0, t; }"
        : "=r"(a) : "l"(p));
    return a;
}

__device__ __forceinline__ void mma_bf16(float* c, const uint32_t* a, const uint32_t* b) {
    asm volatile(
        "mma.sync.aligned.m16n8k16.row.col.f32.bf16.bf16.f32 "
        "{%0,%1,%2,%3}, {%4,%5,%6,%7}, {%8,%9}, {%0,%1,%2,%3};"
        : "+f"(c[0]), "+f"(c[1]), "+f"(c[2]), "+f"(c[3])
        : "r"(a[0]), "r"(a[1]), "r"(a[2]), "r"(a[3]), "r"(b[0]), "r"(b[1]));
}

#define LDSM_X4(r0, r1, r2, r3, addr)                                        \
    asm volatile("ldmatrix.sync.aligned.m8n8.x4.shared.b16 {%0,%1,%2,%3}, [%4];" \
                 : "=r"(r0), "=r"(r1), "=r"(r2), "=r"(r3) : "r"(addr))

__device__ __forceinline__ void cp16(uint32_t dst, const void* src) {
    asm volatile("cp.async.cg.shared.global [%0], [%1], 16;" :: "r"(dst), "l"(src));
}
#define CP_COMMIT() asm volatile("cp.async.commit_group;" ::: "memory")
#define CP_WAIT1()  asm volatile("cp.async.wait_group 1;" ::: "memory")
#define CP_WAIT0()  asm volatile("cp.async.wait_group 0;" ::: "memory")

// single-MUFU tanh
__device__ __forceinline__ float tanh_mufu(float x) {
    float y;
    asm("tanh.approx.f32 %0, %1;" : "=f"(y) : "f"(x));
    return y;
}
// 2-MUFU accurate tanh (for the per-block film scalars)
__device__ __forceinline__ float ftanh_fast(float x) {
    float e = __expf(2.0f * x);
    return 1.0f - __fdividef(2.0f, e + 1.0f);
}

// ---------------------------------------------------------------------------
// Merged prep: activation hi/lo split + weight transpose/split in ONE launch.
// ---------------------------------------------------------------------------
#define FEAT4 (Bq * Fq * Dq / 4)
#define TXT4  (Bq * Tq * Dq / 4)
#define SPLIT_BLOCKS ((FEAT4 + TXT4 + 255) / 256)   // 2304
#define TRANS_BLOCKS (32 * 32 * 2)                  // 2048

__global__ void __launch_bounds__(256)
prep_kernel(const float* __restrict__ feat, __nv_bfloat16* __restrict__ fh,
            __nv_bfloat16* __restrict__ fl,
            const float* __restrict__ txt, __nv_bfloat16* __restrict__ th,
            __nv_bfloat16* __restrict__ tl,
            const float* __restrict__ W0, __nv_bfloat16* __restrict__ H0,
            __nv_bfloat16* __restrict__ L0,
            const float* __restrict__ W1, __nv_bfloat16* __restrict__ H1,
            __nv_bfloat16* __restrict__ L1) {
    __shared__ float ts[32][33];
    const int blk = blockIdx.x;
    const int tid = threadIdx.x;

    if (blk < SPLIT_BLOCKS) {
        int i = blk * 256 + tid;
        const float* in;
        __nv_bfloat16 *hi, *lo;
        if (i < FEAT4) {
            in = feat; hi = fh; lo = fl;
        } else if (i < FEAT4 + TXT4) {
            i -= FEAT4;
            in = txt; hi = th; lo = tl;
        } else {
            return;
        }
        float4 v = ((const float4*)in)[i];
        __nv_bfloat16 h0 = __float2bfloat16(v.x);
        __nv_bfloat16 h1 = __float2bfloat16(v.y);
        __nv_bfloat16 h2 = __float2bfloat16(v.z);
        __nv_bfloat16 h3 = __float2bfloat16(v.w);
        __nv_bfloat16 l0 = __float2bfloat16(v.x - __bfloat162float(h0));
        __nv_bfloat16 l1 = __float2bfloat16(v.y - __bfloat162float(h1));
        __nv_bfloat16 l2 = __float2bfloat16(v.z - __bfloat162float(h2));
        __nv_bfloat16 l3 = __float2bfloat16(v.w - __bfloat162float(h3));
        ((__nv_bfloat162*)hi)[2 * i]     = __nv_bfloat162(h0, h1);
        ((__nv_bfloat162*)hi)[2 * i + 1] = __nv_bfloat162(h2, h3);
        ((__nv_bfloat162*)lo)[2 * i]     = __nv_bfloat162(l0, l1);
        ((__nv_bfloat162*)lo)[2 * i + 1] = __nv_bfloat162(l2, l3);
    } else {
        const int idx   = blk - SPLIT_BLOCKS;
        const int which = idx >> 10;            // 0 -> W, 1 -> Ws
        const int tile  = idx & 1023;
        const int n0 = (tile & 31) * 32;
        const int k0 = (tile >> 5) * 32;
        const float* in = which ? W1 : W0;
        __nv_bfloat16* hi = which ? H1 : H0;
        __nv_bfloat16* lo = which ? L1 : L0;
        const int tx = tid & 31, ty = tid >> 5;  // (32, 8)
#pragma unroll
        for (int i = 0; i < 32; i += 8)
            ts[ty + i][tx] = in[(size_t)(k0 + ty + i) * Dq + n0 + tx];
        __syncthreads();
#pragma unroll
        for (int i = 0; i < 32; i += 8) {
            float v = ts[tx][ty + i];           // = W[k0+tx][n0+ty+i]
            __nv_bfloat16 h = __float2bfloat16(v);
            __nv_bfloat16 l = __float2bfloat16(v - __bfloat162float(h));
            size_t o = (size_t)(n0 + ty + i) * Dq + k0 + tx;
            hi[o] = h;
            lo[o] = l;
        }
    }
}

// ---------------------------------------------------------------------------
// bf16x3 emulated-fp32 GEMM on mma.sync (m16n8k16 bf16).
// CTA tile 128(m) x 128(n), BK=32, 2-stage cp.async pipeline,
// 512 threads (16 warps, 4x4 warp grid, warp tile 32x32), 1 CTA/SM,
// grid (8,18) = 144 CTAs = one wave. Halves L2 traffic vs the 128x64 tile.
// PDL: griddepsync gates the first read of prep outputs.
// ---------------------------------------------------------------------------
#define BK 32
#define NC (Dq / BK)                 // 32
#define ROWB 80                      // 32 bf16 = 64B + 16B pad (conflict-free)
#define TILE128 (128 * ROWB)         // 10240
#define OFF_AH 0
#define OFF_AL TILE128
#define OFF_BH (2 * TILE128)
#define OFF_BL (3 * TILE128)
#define STAGEB (4 * TILE128)         // 40960
#define SMEM_GEMM (2 * STAGEB)       // 81920

// 128 rows x 4 chunks of 16B; 512 threads -> exactly one cp16 per thread.
__device__ __forceinline__ void cp_tile128(uint32_t s, const __nv_bfloat16* __restrict__ g,
                                           int row0, int kc, int tid) {
    int r = tid >> 2, c = tid & 3;
    cp16(s + r * ROWB + c * 16, g + (size_t)(row0 + r) * Dq + kc + c * 8);
}

__device__ __forceinline__ void issue_chunk(uint32_t base,
                                            const __nv_bfloat16* Ah, const __nv_bfloat16* Al,
                                            const __nv_bfloat16* Bh, const __nv_bfloat16* Bl,
                                            int m0, int n0, int kc, int tid) {
    cp_tile128(base + OFF_AH, Ah, m0, kc, tid);
    cp_tile128(base + OFF_AL, Al, m0, kc, tid);
    cp_tile128(base + OFF_BH, Bh, n0, kc, tid);
    cp_tile128(base + OFF_BL, Bl, n0, kc, tid);
    CP_COMMIT();
}

__global__ void __launch_bounds__(512, 1)
mma_gemm_kernel(const __nv_bfloat16* __restrict__ A2h, const __nv_bfloat16* __restrict__ A2l,
                const __nv_bfloat16* __restrict__ B2h, const __nv_bfloat16* __restrict__ B2l,
                float* __restrict__ C2,
                const __nv_bfloat16* __restrict__ A1h, const __nv_bfloat16* __restrict__ A1l,
                const __nv_bfloat16* __restrict__ B1h, const __nv_bfloat16* __restrict__ B1l,
                float* __restrict__ C1, const float* __restrict__ bias1) {
    extern __shared__ char sm[];
    const uint32_t smb = smem_to_u32(sm);
    const int tid  = threadIdx.x;
    const int wid  = tid >> 5;            // 0..15
    const int lane = tid & 31;

    const bool st1 = (blockIdx.y >= 16);
    const int  m0  = st1 ? (int)(blockIdx.y - 16) * 128 : (int)blockIdx.y * 128;
    const int  n0  = blockIdx.x * 128;
    const __nv_bfloat16* Ah = st1 ? A1h : A2h;
    const __nv_bfloat16* Al = st1 ? A1l : A2l;
    const __nv_bfloat16* Bh = st1 ? B1h : B2h;
    const __nv_bfloat16* Bl = st1 ? B1l : B2l;
    float* C = st1 ? C1 : C2;

    const int wm = (wid >> 2) * 32;       // warp m offset (4 rows of warps)
    const int wn = (wid & 3) * 32;        // warp n offset (4 cols of warps)

    float acc[2][4][4];
#pragma unroll
    for (int i = 0; i < 2; i++)
#pragma unroll
        for (int j = 0; j < 4; j++)
#pragma unroll
            for (int k = 0; k < 4; k++) acc[i][j][k] = 0.0f;

    // PDL: wait for prep to fully commit its outputs before first read.
    cudaGridDependencySynchronize();

    // prologue: chunk 0
    issue_chunk(smb, Ah, Al, Bh, Bl, m0, n0, 0, tid);

    const int lg = lane >> 3;             // 0..3
    const int lr = lane & 7;

    for (int c = 0; c < NC; c++) {
        if (c + 1 < NC) {
            issue_chunk(smb + ((c + 1) & 1) * STAGEB, Ah, Al, Bh, Bl,
                        m0, n0, (c + 1) * BK, tid);
            CP_WAIT1();
        } else {
            CP_WAIT0();
        }
        __syncthreads();

        const uint32_t base = smb + (c & 1) * STAGEB;

#pragma unroll
        for (int ks = 0; ks < 2; ks++) {
            const int k0 = ks * 16;
            // B fragments: 4 n-tiles (n8 each) via 2 x4 ldmatrix per hi/lo
            uint32_t bH[4][2], bL[4][2];
            const uint32_t b_off =
                (uint32_t)((wn + ((lg >> 1) << 3) + lr) * ROWB + (k0 + ((lg & 1) << 3)) * 2);
#pragma unroll
            for (int p = 0; p < 2; p++) {
                LDSM_X4(bH[2 * p][0], bH[2 * p][1], bH[2 * p + 1][0], bH[2 * p + 1][1],
                        base + OFF_BH + b_off + p * 16 * ROWB);
                LDSM_X4(bL[2 * p][0], bL[2 * p][1], bL[2 * p + 1][0], bL[2 * p + 1][1],
                        base + OFF_BL + b_off + p * 16 * ROWB);
            }
            const uint32_t a_off =
                (uint32_t)((wm + ((lg & 1) << 3) + lr) * ROWB + (k0 + ((lg >> 1) << 3)) * 2);
#pragma unroll
            for (int mt = 0; mt < 2; mt++) {
                uint32_t aH[4], aL[4];
                LDSM_X4(aH[0], aH[1], aH[2], aH[3],
                        base + OFF_AH + a_off + mt * 16 * ROWB);
                LDSM_X4(aL[0], aL[1], aL[2], aL[3],
                        base + OFF_AL + a_off + mt * 16 * ROWB);
#pragma unroll
                for (int nt = 0; nt < 4; nt++) {
                    mma_bf16(acc[mt][nt], aH, bH[nt]);
                    mma_bf16(acc[mt][nt], aH, bL[nt]);
                    mma_bf16(acc[mt][nt], aL, bH[nt]);
                }
            }
        }
        __syncthreads();
    }

    // Epilogue
    const int row_base = m0 + wm + (lane >> 2);
    const int col_base = n0 + wn + (lane & 3) * 2;
#pragma unroll
    for (int mt = 0; mt < 2; mt++) {
#pragma unroll
        for (int nt = 0; nt < 4; nt++) {
            const int r = row_base + mt * 16;
            const int cc = col_base + nt * 8;
            float2 v01 = make_float2(acc[mt][nt][0], acc[mt][nt][1]);
            float2 v23 = make_float2(acc[mt][nt][2], acc[mt][nt][3]);
            if (st1) {
                float b0 = __ldg(&bias1[cc]);
                float b1 = __ldg(&bias1[cc + 1]);
                v01.x += b0; v01.y += b1;
                v23.x += b0; v23.y += b1;
            }
            *(float2*)&C[(size_t)r * Dq + cc] = v01;
            *(float2*)&C[(size_t)(r + 8) * Dq + cc] = v23;
        }
    }
}

// ---------------------------------------------------------------------------
// Fused attention epilogue, 8 frames per block, single wave (grid 256).
// R12-exact body.
// ---------------------------------------------------------------------------
#define FPB 8
__global__ void __launch_bounds__(256, 2)
attn_kernel(const float* __restrict__ feat,
            const float* __restrict__ txt,
            const int*   __restrict__ qmask,
            const float* __restrict__ wv,
            const float* __restrict__ Wcw, const float* __restrict__ bcw,
            const float* __restrict__ Wcb, const float* __restrict__ bcb,
            float* __restrict__ out) {
    const int f0   = blockIdx.x * FPB;     // base bf index
    const int b    = f0 >> 8;              // F = 256
    const int tid  = threadIdx.x;
    const int warp = tid >> 5;
    const int lane = tid & 31;

    __shared__ float fp_s[FPB][Dq];        // 32 KB
    __shared__ float wv_s[Dq];             // 4 KB
    __shared__ float rho_s[FPB][Tq];
    __shared__ float red_s[2][FPB][8];
    __shared__ float scal_s[FPB][2];

    // PDL: wait for the GEMM grid to finish before consuming g_fp / g_tpp.
    cudaGridDependencySynchronize();

    {
        const int i = tid * 4;
#pragma unroll
        for (int j = 0; j < FPB; j++)
            *(float4*)&fp_s[j][i] = *(const float4*)&g_fp[(size_t)(f0 + j) * Dq + i];
        *(float4*)&wv_s[i] = *(const float4*)&wv[i];
    }
    __syncthreads();

    // rho[j][t] = sum_d tanh(fp[j][d] + tpp[t][d]) * w[d]
    const float* tpp = g_tpp + (size_t)b * Tq * Dq;
    for (int t = warp; t < Tq; t += 8) {
        const float* tr = tpp + (size_t)t * Dq;
        float a[FPB];
#pragma unroll
        for (int j = 0; j < FPB; j++) a[j] = 0.0f;
#pragma unroll 2
        for (int d = lane * 4; d < Dq; d += 128) {
            float4 tv = *(const float4*)&tr[d];
            float4 w4 = *(const float4*)&wv_s[d];
#pragma unroll
            for (int j = 0; j < FPB; j++) {
                float4 f4 = *(const float4*)&fp_s[j][d];
                a[j] += tanh_mufu(f4.x + tv.x) * w4.x + tanh_mufu(f4.y + tv.y) * w4.y
                      + tanh_mufu(f4.z + tv.z) * w4.z + tanh_mufu(f4.w + tv.w) * w4.w;
            }
        }
#pragma unroll
        for (int o = 16; o; o >>= 1)
#pragma unroll
            for (int j = 0; j < FPB; j++)
                a[j] += __shfl_xor_sync(0xffffffffu, a[j], o);
        if (lane == 0) {
            float m = (float)qmask[b * Tq + t];
            float msk = (1.0f - m) * NEGV;
#pragma unroll
            for (int j = 0; j < FPB; j++)
                rho_s[j][t] = a[j] + msk;
        }
    }
    __syncthreads();

    // softmax over T=32 (warps 0..7, one frame each)
    {
        float v = rho_s[warp][lane];
        float mx = v;
#pragma unroll
        for (int o = 16; o; o >>= 1)
            mx = fmaxf(mx, __shfl_xor_sync(0xffffffffu, mx, o));
        float e = __expf(v - mx);
        float s = e;
#pragma unroll
        for (int o = 16; o; o >>= 1)
            s += __shfl_xor_sync(0xffffffffu, s, o);
        rho_s[warp][lane] = e / s;
    }
    __syncthreads();

    // txt_h[j] + two dot products
    const int d0 = tid * 4;
    float4 th[FPB];
#pragma unroll
    for (int j = 0; j < FPB; j++) th[j] = make_float4(0.f, 0.f, 0.f, 0.f);
    const float* tb = txt + (size_t)b * Tq * Dq + d0;
#pragma unroll 2
    for (int t = 0; t < Tq; t++) {
        float4 v = *(const float4*)(tb + (size_t)t * Dq);
#pragma unroll
        for (int j = 0; j < FPB; j++) {
            const float a = rho_s[j][t];
            th[j].x = fmaf(a, v.x, th[j].x);
            th[j].y = fmaf(a, v.y, th[j].y);
            th[j].z = fmaf(a, v.z, th[j].z);
            th[j].w = fmaf(a, v.w, th[j].w);
        }
    }
    float4 cw = *(const float4*)&Wcw[d0];
    float4 cb = *(const float4*)&Wcb[d0];
#pragma unroll
    for (int j = 0; j < FPB; j++) {
        float dw = th[j].x * cw.x + th[j].y * cw.y + th[j].z * cw.z + th[j].w * cw.w;
        float db = th[j].x * cb.x + th[j].y * cb.y + th[j].z * cb.z + th[j].w * cb.w;
#pragma unroll
        for (int o = 16; o; o >>= 1) {
            dw += __shfl_xor_sync(0xffffffffu, dw, o);
            db += __shfl_xor_sync(0xffffffffu, db, o);
        }
        if (lane == 0) {
            red_s[0][j][warp] = dw;
            red_s[1][j][warp] = db;
        }
    }
    __syncthreads();
    if (tid < FPB) {
        float sw = 0.f, sb = 0.f;
#pragma unroll
        for (int i = 0; i < 8; i++) {
            sw += red_s[0][tid][i];
            sb += red_s[1][tid][i];
        }
        scal_s[tid][0] = ftanh_fast(sw + bcw[0]);
        scal_s[tid][1] = ftanh_fast(sb + bcb[0]);
    }
    __syncthreads();

#pragma unroll
    for (int j = 0; j < FPB; j++) {
        const float ws = scal_s[j][0];
        const float bs = scal_s[j][1];
        float4 f = *(const float4*)&feat[(size_t)(f0 + j) * Dq + d0];
        float4 o4;
        o4.x = fmaf(ws, f.x, bs);
        o4.y = fmaf(ws, f.y, bs);
        o4.z = fmaf(ws, f.z, bs);
        o4.w = fmaf(ws, f.w, bs);
        *(float4*)&out[(size_t)(f0 + j) * Dq + d0] = o4;
    }
}

// ---------------------------------------------------------------------------
extern "C" void kernel_launch(void* const* d_in, const int* in_sizes, int n_in,
                              void* d_out, int out_size) {
    const float* features = (const float*)d_in[0];
    const float* txt      = (const float*)d_in[2];
    const int*   qm       = (const int*)  d_in[3];
    const float* Ws       = (const float*)d_in[4];
    const float* W        = (const float*)d_in[5];
    const float* wvec     = (const float*)d_in[6];
    const float* bvec     = (const float*)d_in[7];
    const float* Wcw      = (const float*)d_in[8];
    const float* bcw      = (const float*)d_in[9];
    const float* Wcb      = (const float*)d_in[10];
    const float* bcb      = (const float*)d_in[11];
    float* out = (float*)d_out;

    float *tpp_p, *fp_p;
    __nv_bfloat16 *fh, *fl, *th, *tl, *wth, *wtl, *wsh, *wsl;
    cudaGetSymbolAddress((void**)&tpp_p, g_tpp);
    cudaGetSymbolAddress((void**)&fp_p,  g_fp);
    cudaGetSymbolAddress((void**)&fh,  g_fh);
    cudaGetSymbolAddress((void**)&fl,  g_fl);
    cudaGetSymbolAddress((void**)&th,  g_th);
    cudaGetSymbolAddress((void**)&tl,  g_tl);
    cudaGetSymbolAddress((void**)&wth, g_wth);
    cudaGetSymbolAddress((void**)&wtl, g_wtl);
    cudaGetSymbolAddress((void**)&wsh, g_wsh);
    cudaGetSymbolAddress((void**)&wsl, g_wsl);

    cudaFuncSetAttribute(mma_gemm_kernel,
                         cudaFuncAttributeMaxDynamicSharedMemorySize, SMEM_GEMM);

    // 1) merged prep: activation split + weight transpose/split (one launch)
    prep_kernel<<<SPLIT_BLOCKS + TRANS_BLOCKS, 256>>>(
        features, fh, fl, txt, th, tl,
        W, wth, wtl, Ws, wsh, wsl);

    // PDL attribute
    cudaLaunchAttribute pdl[1];
    pdl[0].id = cudaLaunchAttributeProgrammaticStreamSerialization;
    pdl[0].val.programmaticStreamSerializationAllowed = 1;

    // 2) merged mma.sync GEMM, 128x128 tiles, 144 CTAs (one wave), 512 thr
    {
        cudaLaunchConfig_t cfg = {};
        cfg.gridDim = dim3(Dq / 128, 18);
        cfg.blockDim = dim3(512);
        cfg.dynamicSmemBytes = SMEM_GEMM;
        cfg.stream = 0;
        cfg.attrs = pdl;
        cfg.numAttrs = 1;
        cudaLaunchKernelEx(&cfg, mma_gemm_kernel,
                           (const __nv_bfloat16*)fh, (const __nv_bfloat16*)fl,
                           (const __nv_bfloat16*)wth, (const __nv_bfloat16*)wtl,
                           fp_p,
                           (const __nv_bfloat16*)th, (const __nv_bfloat16*)tl,
                           (const __nv_bfloat16*)wsh, (const __nv_bfloat16*)wsl,
                           tpp_p, bvec);
    }

    // 3) fused attention + film epilogue — PDL-overlapped with GEMM tail
    {
        cudaLaunchConfig_t cfg = {};
        cfg.gridDim = dim3(Bq * Fq / FPB);
        cfg.blockDim = dim3(256);
        cfg.dynamicSmemBytes = 0;
        cfg.stream = 0;
        cfg.attrs = pdl;
        cfg.numAttrs = 1;
        cudaLaunchKernelEx(&cfg, attn_kernel,
                           features, txt, qm, wvec,
                           Wcw, bcw, Wcb, bcb, out);
    }
}

// round 17
// speedup vs baseline: 1.2429x; 1.0004x over previous
#include <cuda_runtime.h>
#include <cuda_bf16.h>
#include <cstdint>

// Problem constants
#define Bq 8
#define Fq 256
#define Tq 32
#define Dq 1024
#define NEGV (-1e30f)

// ---------------------------------------------------------------------------
// Device-global scratch (no allocation allowed)
// ---------------------------------------------------------------------------
__device__ float g_tpp[Bq * Tq * Dq];            // txt@Ws + b     (1 MB)
__device__ float g_fp [Bq * Fq * Dq];            // feat@W         (8 MB)

__device__ __nv_bfloat16 g_fh [Bq * Fq * Dq];    // feat hi
__device__ __nv_bfloat16 g_fl [Bq * Fq * Dq];    // feat lo
__device__ __nv_bfloat16 g_th [Bq * Tq * Dq];    // txt hi
__device__ __nv_bfloat16 g_tl [Bq * Tq * Dq];    // txt lo
__device__ __nv_bfloat16 g_wth[Dq * Dq];         // W^T hi  ([n][k])
__device__ __nv_bfloat16 g_wtl[Dq * Dq];         // W^T lo
__device__ __nv_bfloat16 g_wsh[Dq * Dq];         // Ws^T hi
__device__ __nv_bfloat16 g_wsl[Dq * Dq];         // Ws^T lo

// ---------------------------------------------------------------------------
// Helpers
// ---------------------------------------------------------------------------
__device__ __forceinline__ uint32_t smem_to_u32(const void* p) {
    uint32_t a;
    asm("{ .reg .u64 t; cvta.to.shared.u64 t, %1; cvt.u32.u64 %0, t; }"
        : "=r"(a) : "l"(p));
    return a;
}

__device__ __forceinline__ void mma_bf16(float* c, const uint32_t* a, const uint32_t* b) {
    asm volatile(
        "mma.sync.aligned.m16n8k16.row.col.f32.bf16.bf16.f32 "
        "{%0,%1,%2,%3}, {%4,%5,%6,%7}, {%8,%9}, {%0,%1,%2,%3};"
        : "+f"(c[0]), "+f"(c[1]), "+f"(c[2]), "+f"(c[3])
        : "r"(a[0]), "r"(a[1]), "r"(a[2]), "r"(a[3]), "r"(b[0]), "r"(b[1]));
}

#define LDSM_X4(r0, r1, r2, r3, addr)                                        \
    asm volatile("ldmatrix.sync.aligned.m8n8.x4.shared.b16 {%0,%1,%2,%3}, [%4];" \
                 : "=r"(r0), "=r"(r1), "=r"(r2), "=r"(r3) : "r"(addr))

__device__ __forceinline__ void cp16(uint32_t dst, const void* src) {
    asm volatile("cp.async.cg.shared.global [%0], [%1], 16;" :: "r"(dst), "l"(src));
}
#define CP_COMMIT() asm volatile("cp.async.commit_group;" ::: "memory")
#define CP_WAIT1()  asm volatile("cp.async.wait_group 1;" ::: "memory")
#define CP_WAIT0()  asm volatile("cp.async.wait_group 0;" ::: "memory")

// single-MUFU tanh
__device__ __forceinline__ float tanh_mufu(float x) {
    float y;
    asm("tanh.approx.f32 %0, %1;" : "=f"(y) : "f"(x));
    return y;
}
// 2-MUFU accurate tanh (for the per-block film scalars)
__device__ __forceinline__ float ftanh_fast(float x) {
    float e = __expf(2.0f * x);
    return 1.0f - __fdividef(2.0f, e + 1.0f);
}

// pack two floats' bf16 into one uint
__device__ __forceinline__ uint32_t pack_bf16_hi(float a, float b) {
    __nv_bfloat162 p(__float2bfloat16(a), __float2bfloat16(b));
    return *(uint32_t*)&p;
}

// ---------------------------------------------------------------------------
// Merged prep v2: wide-store activation split + weight transpose/split.
//   Split path: 8 floats/thread, one 16B store per hi/lo buffer.
//   Transpose path: threads 0-127 own (n, 8k) after the smem tile, one 16B
//   store per hi/lo buffer.
// ---------------------------------------------------------------------------
#define FEATN (Bq * Fq * Dq)
#define TXTN  (Bq * Tq * Dq)
#define FEAT8 (FEATN / 8)                        // 262144
#define TXT8  (TXTN / 8)                         // 32768
#define SPLIT_BLOCKS ((FEAT8 + TXT8) / 256)      // 1152
#define TRANS_BLOCKS (32 * 32 * 2)               // 2048

__global__ void __launch_bounds__(256)
prep_kernel(const float* __restrict__ feat, __nv_bfloat16* __restrict__ fh,
            __nv_bfloat16* __restrict__ fl,
            const float* __restrict__ txt, __nv_bfloat16* __restrict__ th,
            __nv_bfloat16* __restrict__ tl,
            const float* __restrict__ W0, __nv_bfloat16* __restrict__ H0,
            __nv_bfloat16* __restrict__ L0,
            const float* __restrict__ W1, __nv_bfloat16* __restrict__ H1,
            __nv_bfloat16* __restrict__ L1) {
    __shared__ float ts[32][33];
    const int blk = blockIdx.x;
    const int tid = threadIdx.x;

    if (blk < SPLIT_BLOCKS) {
        int p = blk * 256 + tid;                 // unit of 8 floats
        const float* in;
        __nv_bfloat16 *hi, *lo;
        if (p < FEAT8) {
            in = feat; hi = fh; lo = fl;
        } else {
            p -= FEAT8;
            in = txt; hi = th; lo = tl;
        }
        float4 a = ((const float4*)in)[2 * p];
        float4 b = ((const float4*)in)[2 * p + 1];
        float av[8] = {a.x, a.y, a.z, a.w, b.x, b.y, b.z, b.w};
        uint32_t hw[4], lw[4];
#pragma unroll
        for (int q = 0; q < 4; q++) {
            float x = av[2 * q], y = av[2 * q + 1];
            __nv_bfloat16 hx = __float2bfloat16(x);
            __nv_bfloat16 hy = __float2bfloat16(y);
            hw[q] = pack_bf16_hi(x, y);
            lw[q] = pack_bf16_hi(x - __bfloat162float(hx), y - __bfloat162float(hy));
        }
        ((uint4*)hi)[p] = make_uint4(hw[0], hw[1], hw[2], hw[3]);
        ((uint4*)lo)[p] = make_uint4(lw[0], lw[1], lw[2], lw[3]);
    } else {
        const int idx   = blk - SPLIT_BLOCKS;
        const int which = idx >> 10;             // 0 -> W, 1 -> Ws
        const int tile  = idx & 1023;
        const int n0 = (tile & 31) * 32;
        const int k0 = (tile >> 5) * 32;
        const float* in = which ? W1 : W0;
        __nv_bfloat16* hi = which ? H1 : H0;
        __nv_bfloat16* lo = which ? L1 : L0;
        const int tx = tid & 31, ty = tid >> 5;  // (32, 8) loaders
#pragma unroll
        for (int i = 0; i < 32; i += 8)
            ts[ty + i][tx] = in[(size_t)(k0 + ty + i) * Dq + n0 + tx];
        __syncthreads();
        if (tid < 128) {
            const int n  = tid >> 2;             // 0..31
            const int kc = tid & 3;              // 0..3 (8 k each)
            uint32_t hw[4], lw[4];
#pragma unroll
            for (int q = 0; q < 4; q++) {
                float x = ts[kc * 8 + 2 * q][n];      // = W[k0+..][n0+n]
                float y = ts[kc * 8 + 2 * q + 1][n];
                __nv_bfloat16 hx = __float2bfloat16(x);
                __nv_bfloat16 hy = __float2bfloat16(y);
                hw[q] = pack_bf16_hi(x, y);
                lw[q] = pack_bf16_hi(x - __bfloat162float(hx), y - __bfloat162float(hy));
            }
            size_t o = ((size_t)(n0 + n) * Dq + k0 + kc * 8) / 8;  // uint4 index
            ((uint4*)hi)[o] = make_uint4(hw[0], hw[1], hw[2], hw[3]);
            ((uint4*)lo)[o] = make_uint4(lw[0], lw[1], lw[2], lw[3]);
        }
    }
}

// ---------------------------------------------------------------------------
// bf16x3 emulated-fp32 GEMM on mma.sync (m16n8k16 bf16).
// CTA tile 128(m) x 128(n), BK=32, 2-stage cp.async pipeline,
// 512 threads (16 warps, 4x4 warp grid, warp tile 32x32), 1 CTA/SM,
// grid (8,18) = 144 CTAs = one wave. (R16-exact)
// ---------------------------------------------------------------------------
#define BK 32
#define NC (Dq / BK)                 // 32
#define ROWB 80                      // 32 bf16 = 64B + 16B pad (conflict-free)
#define TILE128 (128 * ROWB)         // 10240
#define OFF_AH 0
#define OFF_AL TILE128
#define OFF_BH (2 * TILE128)
#define OFF_BL (3 * TILE128)
#define STAGEB (4 * TILE128)         // 40960
#define SMEM_GEMM (2 * STAGEB)       // 81920

__device__ __forceinline__ void cp_tile128(uint32_t s, const __nv_bfloat16* __restrict__ g,
                                           int row0, int kc, int tid) {
    int r = tid >> 2, c = tid & 3;
    cp16(s + r * ROWB + c * 16, g + (size_t)(row0 + r) * Dq + kc + c * 8);
}

__device__ __forceinline__ void issue_chunk(uint32_t base,
                                            const __nv_bfloat16* Ah, const __nv_bfloat16* Al,
                                            const __nv_bfloat16* Bh, const __nv_bfloat16* Bl,
                                            int m0, int n0, int kc, int tid) {
    cp_tile128(base + OFF_AH, Ah, m0, kc, tid);
    cp_tile128(base + OFF_AL, Al, m0, kc, tid);
    cp_tile128(base + OFF_BH, Bh, n0, kc, tid);
    cp_tile128(base + OFF_BL, Bl, n0, kc, tid);
    CP_COMMIT();
}

__global__ void __launch_bounds__(512, 1)
mma_gemm_kernel(const __nv_bfloat16* __restrict__ A2h, const __nv_bfloat16* __restrict__ A2l,
                const __nv_bfloat16* __restrict__ B2h, const __nv_bfloat16* __restrict__ B2l,
                float* __restrict__ C2,
                const __nv_bfloat16* __restrict__ A1h, const __nv_bfloat16* __restrict__ A1l,
                const __nv_bfloat16* __restrict__ B1h, const __nv_bfloat16* __restrict__ B1l,
                float* __restrict__ C1, const float* __restrict__ bias1) {
    extern __shared__ char sm[];
    const uint32_t smb = smem_to_u32(sm);
    const int tid  = threadIdx.x;
    const int wid  = tid >> 5;            // 0..15
    const int lane = tid & 31;

    const bool st1 = (blockIdx.y >= 16);
    const int  m0  = st1 ? (int)(blockIdx.y - 16) * 128 : (int)blockIdx.y * 128;
    const int  n0  = blockIdx.x * 128;
    const __nv_bfloat16* Ah = st1 ? A1h : A2h;
    const __nv_bfloat16* Al = st1 ? A1l : A2l;
    const __nv_bfloat16* Bh = st1 ? B1h : B2h;
    const __nv_bfloat16* Bl = st1 ? B1l : B2l;
    float* C = st1 ? C1 : C2;

    const int wm = (wid >> 2) * 32;       // warp m offset
    const int wn = (wid & 3) * 32;        // warp n offset

    float acc[2][4][4];
#pragma unroll
    for (int i = 0; i < 2; i++)
#pragma unroll
        for (int j = 0; j < 4; j++)
#pragma unroll
            for (int k = 0; k < 4; k++) acc[i][j][k] = 0.0f;

    // PDL: wait for prep to fully commit its outputs before first read.
    cudaGridDependencySynchronize();

    // prologue: chunk 0
    issue_chunk(smb, Ah, Al, Bh, Bl, m0, n0, 0, tid);

    const int lg = lane >> 3;             // 0..3
    const int lr = lane & 7;

    for (int c = 0; c < NC; c++) {
        if (c + 1 < NC) {
            issue_chunk(smb + ((c + 1) & 1) * STAGEB, Ah, Al, Bh, Bl,
                        m0, n0, (c + 1) * BK, tid);
            CP_WAIT1();
        } else {
            CP_WAIT0();
        }
        __syncthreads();

        const uint32_t base = smb + (c & 1) * STAGEB;

#pragma unroll
        for (int ks = 0; ks < 2; ks++) {
            const int k0 = ks * 16;
            uint32_t bH[4][2], bL[4][2];
            const uint32_t b_off =
                (uint32_t)((wn + ((lg >> 1) << 3) + lr) * ROWB + (k0 + ((lg & 1) << 3)) * 2);
#pragma unroll
            for (int p = 0; p < 2; p++) {
                LDSM_X4(bH[2 * p][0], bH[2 * p][1], bH[2 * p + 1][0], bH[2 * p + 1][1],
                        base + OFF_BH + b_off + p * 16 * ROWB);
                LDSM_X4(bL[2 * p][0], bL[2 * p][1], bL[2 * p + 1][0], bL[2 * p + 1][1],
                        base + OFF_BL + b_off + p * 16 * ROWB);
            }
            const uint32_t a_off =
                (uint32_t)((wm + ((lg & 1) << 3) + lr) * ROWB + (k0 + ((lg >> 1) << 3)) * 2);
#pragma unroll
            for (int mt = 0; mt < 2; mt++) {
                uint32_t aH[4], aL[4];
                LDSM_X4(aH[0], aH[1], aH[2], aH[3],
                        base + OFF_AH + a_off + mt * 16 * ROWB);
                LDSM_X4(aL[0], aL[1], aL[2], aL[3],
                        base + OFF_AL + a_off + mt * 16 * ROWB);
#pragma unroll
                for (int nt = 0; nt < 4; nt++) {
                    mma_bf16(acc[mt][nt], aH, bH[nt]);
                    mma_bf16(acc[mt][nt], aH, bL[nt]);
                    mma_bf16(acc[mt][nt], aL, bH[nt]);
                }
            }
        }
        __syncthreads();
    }

    // Epilogue
    const int row_base = m0 + wm + (lane >> 2);
    const int col_base = n0 + wn + (lane & 3) * 2;
#pragma unroll
    for (int mt = 0; mt < 2; mt++) {
#pragma unroll
        for (int nt = 0; nt < 4; nt++) {
            const int r = row_base + mt * 16;
            const int cc = col_base + nt * 8;
            float2 v01 = make_float2(acc[mt][nt][0], acc[mt][nt][1]);
            float2 v23 = make_float2(acc[mt][nt][2], acc[mt][nt][3]);
            if (st1) {
                float b0 = __ldg(&bias1[cc]);
                float b1 = __ldg(&bias1[cc + 1]);
                v01.x += b0; v01.y += b1;
                v23.x += b0; v23.y += b1;
            }
            *(float2*)&C[(size_t)r * Dq + cc] = v01;
            *(float2*)&C[(size_t)(r + 8) * Dq + cc] = v23;
        }
    }
}

// ---------------------------------------------------------------------------
// Fused attention epilogue, 8 frames per block, single wave (grid 256).
// R12-exact body.
// ---------------------------------------------------------------------------
#define FPB 8
__global__ void __launch_bounds__(256, 2)
attn_kernel(const float* __restrict__ feat,
            const float* __restrict__ txt,
            const int*   __restrict__ qmask,
            const float* __restrict__ wv,
            const float* __restrict__ Wcw, const float* __restrict__ bcw,
            const float* __restrict__ Wcb, const float* __restrict__ bcb,
            float* __restrict__ out) {
    const int f0   = blockIdx.x * FPB;     // base bf index
    const int b    = f0 >> 8;              // F = 256
    const int tid  = threadIdx.x;
    const int warp = tid >> 5;
    const int lane = tid & 31;

    __shared__ float fp_s[FPB][Dq];        // 32 KB
    __shared__ float wv_s[Dq];             // 4 KB
    __shared__ float rho_s[FPB][Tq];
    __shared__ float red_s[2][FPB][8];
    __shared__ float scal_s[FPB][2];

    // PDL: wait for the GEMM grid to finish before consuming g_fp / g_tpp.
    cudaGridDependencySynchronize();

    {
        const int i = tid * 4;
#pragma unroll
        for (int j = 0; j < FPB; j++)
            *(float4*)&fp_s[j][i] = *(const float4*)&g_fp[(size_t)(f0 + j) * Dq + i];
        *(float4*)&wv_s[i] = *(const float4*)&wv[i];
    }
    __syncthreads();

    // rho[j][t] = sum_d tanh(fp[j][d] + tpp[t][d]) * w[d]
    const float* tpp = g_tpp + (size_t)b * Tq * Dq;
    for (int t = warp; t < Tq; t += 8) {
        const float* tr = tpp + (size_t)t * Dq;
        float a[FPB];
#pragma unroll
        for (int j = 0; j < FPB; j++) a[j] = 0.0f;
#pragma unroll 2
        for (int d = lane * 4; d < Dq; d += 128) {
            float4 tv = *(const float4*)&tr[d];
            float4 w4 = *(const float4*)&wv_s[d];
#pragma unroll
            for (int j = 0; j < FPB; j++) {
                float4 f4 = *(const float4*)&fp_s[j][d];
                a[j] += tanh_mufu(f4.x + tv.x) * w4.x + tanh_mufu(f4.y + tv.y) * w4.y
                      + tanh_mufu(f4.z + tv.z) * w4.z + tanh_mufu(f4.w + tv.w) * w4.w;
            }
        }
#pragma unroll
        for (int o = 16; o; o >>= 1)
#pragma unroll
            for (int j = 0; j < FPB; j++)
                a[j] += __shfl_xor_sync(0xffffffffu, a[j], o);
        if (lane == 0) {
            float m = (float)qmask[b * Tq + t];
            float msk = (1.0f - m) * NEGV;
#pragma unroll
            for (int j = 0; j < FPB; j++)
                rho_s[j][t] = a[j] + msk;
        }
    }
    __syncthreads();

    // softmax over T=32 (warps 0..7, one frame each)
    {
        float v = rho_s[warp][lane];
        float mx = v;
#pragma unroll
        for (int o = 16; o; o >>= 1)
            mx = fmaxf(mx, __shfl_xor_sync(0xffffffffu, mx, o));
        float e = __expf(v - mx);
        float s = e;
#pragma unroll
        for (int o = 16; o; o >>= 1)
            s += __shfl_xor_sync(0xffffffffu, s, o);
        rho_s[warp][lane] = e / s;
    }
    __syncthreads();

    // txt_h[j] + two dot products
    const int d0 = tid * 4;
    float4 th[FPB];
#pragma unroll
    for (int j = 0; j < FPB; j++) th[j] = make_float4(0.f, 0.f, 0.f, 0.f);
    const float* tb = txt + (size_t)b * Tq * Dq + d0;
#pragma unroll 2
    for (int t = 0; t < Tq; t++) {
        float4 v = *(const float4*)(tb + (size_t)t * Dq);
#pragma unroll
        for (int j = 0; j < FPB; j++) {
            const float a = rho_s[j][t];
            th[j].x = fmaf(a, v.x, th[j].x);
            th[j].y = fmaf(a, v.y, th[j].y);
            th[j].z = fmaf(a, v.z, th[j].z);
            th[j].w = fmaf(a, v.w, th[j].w);
        }
    }
    float4 cw = *(const float4*)&Wcw[d0];
    float4 cb = *(const float4*)&Wcb[d0];
#pragma unroll
    for (int j = 0; j < FPB; j++) {
        float dw = th[j].x * cw.x + th[j].y * cw.y + th[j].z * cw.z + th[j].w * cw.w;
        float db = th[j].x * cb.x + th[j].y * cb.y + th[j].z * cb.z + th[j].w * cb.w;
#pragma unroll
        for (int o = 16; o; o >>= 1) {
            dw += __shfl_xor_sync(0xffffffffu, dw, o);
            db += __shfl_xor_sync(0xffffffffu, db, o);
        }
        if (lane == 0) {
            red_s[0][j][warp] = dw;
            red_s[1][j][warp] = db;
        }
    }
    __syncthreads();
    if (tid < FPB) {
        float sw = 0.f, sb = 0.f;
#pragma unroll
        for (int i = 0; i < 8; i++) {
            sw += red_s[0][tid][i];
            sb += red_s[1][tid][i];
        }
        scal_s[tid][0] = ftanh_fast(sw + bcw[0]);
        scal_s[tid][1] = ftanh_fast(sb + bcb[0]);
    }
    __syncthreads();

#pragma unroll
    for (int j = 0; j < FPB; j++) {
        const float ws = scal_s[j][0];
        const float bs = scal_s[j][1];
        float4 f = *(const float4*)&feat[(size_t)(f0 + j) * Dq + d0];
        float4 o4;
        o4.x = fmaf(ws, f.x, bs);
        o4.y = fmaf(ws, f.y, bs);
        o4.z = fmaf(ws, f.z, bs);
        o4.w = fmaf(ws, f.w, bs);
        *(float4*)&out[(size_t)(f0 + j) * Dq + d0] = o4;
    }
}

// ---------------------------------------------------------------------------
extern "C" void kernel_launch(void* const* d_in, const int* in_sizes, int n_in,
                              void* d_out, int out_size) {
    const float* features = (const float*)d_in[0];
    const float* txt      = (const float*)d_in[2];
    const int*   qm       = (const int*)  d_in[3];
    const float* Ws       = (const float*)d_in[4];
    const float* W        = (const float*)d_in[5];
    const float* wvec     = (const float*)d_in[6];
    const float* bvec     = (const float*)d_in[7];
    const float* Wcw      = (const float*)d_in[8];
    const float* bcw      = (const float*)d_in[9];
    const float* Wcb      = (const float*)d_in[10];
    const float* bcb      = (const float*)d_in[11];
    float* out = (float*)d_out;

    float *tpp_p, *fp_p;
    __nv_bfloat16 *fh, *fl, *th, *tl, *wth, *wtl, *wsh, *wsl;
    cudaGetSymbolAddress((void**)&tpp_p, g_tpp);
    cudaGetSymbolAddress((void**)&fp_p,  g_fp);
    cudaGetSymbolAddress((void**)&fh,  g_fh);
    cudaGetSymbolAddress((void**)&fl,  g_fl);
    cudaGetSymbolAddress((void**)&th,  g_th);
    cudaGetSymbolAddress((void**)&tl,  g_tl);
    cudaGetSymbolAddress((void**)&wth, g_wth);
    cudaGetSymbolAddress((void**)&wtl, g_wtl);
    cudaGetSymbolAddress((void**)&wsh, g_wsh);
    cudaGetSymbolAddress((void**)&wsl, g_wsl);

    cudaFuncSetAttribute(mma_gemm_kernel,
                         cudaFuncAttributeMaxDynamicSharedMemorySize, SMEM_GEMM);

    // 1) merged prep: wide-store activation split + weight transpose/split
    prep_kernel<<<SPLIT_BLOCKS + TRANS_BLOCKS, 256>>>(
        features, fh, fl, txt, th, tl,
        W, wth, wtl, Ws, wsh, wsl);

    // PDL attribute
    cudaLaunchAttribute pdl[1];
    pdl[0].id = cudaLaunchAttributeProgrammaticStreamSerialization;
    pdl[0].val.programmaticStreamSerializationAllowed = 1;

    // 2) merged mma.sync GEMM, 128x128 tiles, 144 CTAs (one wave), 512 thr
    {
        cudaLaunchConfig_t cfg = {};
        cfg.gridDim = dim3(Dq / 128, 18);
        cfg.blockDim = dim3(512);
        cfg.dynamicSmemBytes = SMEM_GEMM;
        cfg.stream = 0;
        cfg.attrs = pdl;
        cfg.numAttrs = 1;
        cudaLaunchKernelEx(&cfg, mma_gemm_kernel,
                           (const __nv_bfloat16*)fh, (const __nv_bfloat16*)fl,
                           (const __nv_bfloat16*)wth, (const __nv_bfloat16*)wtl,
                           fp_p,
                           (const __nv_bfloat16*)th, (const __nv_bfloat16*)tl,
                           (const __nv_bfloat16*)wsh, (const __nv_bfloat16*)wsl,
                           tpp_p, bvec);
    }

    // 3) fused attention + film epilogue — PDL-overlapped with GEMM tail
    {
        cudaLaunchConfig_t cfg = {};
        cfg.gridDim = dim3(Bq * Fq / FPB);
        cfg.blockDim = dim3(256);
        cfg.dynamicSmemBytes = 0;
        cfg.stream = 0;
        cfg.attrs = pdl;
        cfg.numAttrs = 1;
        cudaLaunchKernelEx(&cfg, attn_kernel,
                           features, txt, qm, wvec,
                           Wcw, bcw, Wcb, bcb, out);
    }
}